// round 2
// baseline (speedup 1.0000x reference)
#include <cuda_runtime.h>
#include <math.h>

// ---------------------------------------------------------------------------
// NAS-controller LSTM (48 sequential steps) as ONE persistent kernel.
//  - precompute P1 = emb @ W_ih1^T  (23 x 8192) once -> kills W_ih1 traffic
//  - per step: phase1 = W_hh1*h1 + W_hh2*h2 dots (128MB), phase2 = W_ih2*h1 (64MB)
//  - grid-stride work loops + occupancy-derived grid  => barrier cannot deadlock
//  - threefry2x32 PRNG reproduced bit-exactly (JAX partitionable path)
// ---------------------------------------------------------------------------

#ifndef JAX_PARTITIONABLE
#define JAX_PARTITIONABLE 1   // JAX >= 0.5 default. Set 0 for legacy threefry split.
#endif

#define HD    2048
#define H4    8192
#define ED    512
#define TT    48
#define MAXS  8
#define NEMB  23
#define NTH   1024
#define NWARPS (NTH / 32)

#define TINYF 1.17549435e-38f

// ------------------------- device scratch (static, no allocs) --------------
__device__ float    g_P1[NEMB * H4];   // precomputed emb @ W_ih1^T
__device__ float    g_h1[HD];
__device__ float    g_h2[HD];
__device__ float    g_c1[HD];
__device__ float    g_c2[HD];
__device__ float    g_w2[H4];          // layer-2 hh gate partials
__device__ unsigned g_count = 0;
__device__ unsigned g_gen   = 0;

// ------------------------- grid barrier ------------------------------------
__device__ __forceinline__ void grid_sync() {
  __threadfence();
  __syncthreads();
  if (threadIdx.x == 0) {
    volatile unsigned* vg = (volatile unsigned*)&g_gen;
    unsigned gen = *vg;
    __threadfence();
    if (atomicAdd(&g_count, 1u) == (unsigned)(gridDim.x - 1)) {
      g_count = 0u;
      __threadfence();
      atomicAdd(&g_gen, 1u);
    } else {
      while (*vg == gen) { __nanosleep(64); }
    }
  }
  __syncthreads();
}

// ------------------------- threefry2x32 (exact JAX semantics) ---------------
__device__ __forceinline__ unsigned rotl32(unsigned x, int r) {
  return (x << r) | (x >> (32 - r));
}

__device__ __forceinline__ void threefry2x32(unsigned k0, unsigned k1,
                                             unsigned x0, unsigned x1,
                                             unsigned* o0, unsigned* o1) {
  unsigned ks0 = k0, ks1 = k1, ks2 = k0 ^ k1 ^ 0x1BD11BDAu;
  x0 += ks0; x1 += ks1;
  x0 += x1; x1 = rotl32(x1, 13); x1 ^= x0;
  x0 += x1; x1 = rotl32(x1, 15); x1 ^= x0;
  x0 += x1; x1 = rotl32(x1, 26); x1 ^= x0;
  x0 += x1; x1 = rotl32(x1, 6);  x1 ^= x0;
  x0 += ks1; x1 += ks2 + 1u;
  x0 += x1; x1 = rotl32(x1, 17); x1 ^= x0;
  x0 += x1; x1 = rotl32(x1, 29); x1 ^= x0;
  x0 += x1; x1 = rotl32(x1, 16); x1 ^= x0;
  x0 += x1; x1 = rotl32(x1, 24); x1 ^= x0;
  x0 += ks2; x1 += ks0 + 2u;
  x0 += x1; x1 = rotl32(x1, 13); x1 ^= x0;
  x0 += x1; x1 = rotl32(x1, 15); x1 ^= x0;
  x0 += x1; x1 = rotl32(x1, 26); x1 ^= x0;
  x0 += x1; x1 = rotl32(x1, 6);  x1 ^= x0;
  x0 += ks0; x1 += ks1 + 3u;
  x0 += x1; x1 = rotl32(x1, 17); x1 ^= x0;
  x0 += x1; x1 = rotl32(x1, 29); x1 ^= x0;
  x0 += x1; x1 = rotl32(x1, 16); x1 ^= x0;
  x0 += x1; x1 = rotl32(x1, 24); x1 ^= x0;
  x0 += ks1; x1 += ks2 + 4u;
  x0 += x1; x1 = rotl32(x1, 13); x1 ^= x0;
  x0 += x1; x1 = rotl32(x1, 15); x1 ^= x0;
  x0 += x1; x1 = rotl32(x1, 26); x1 ^= x0;
  x0 += x1; x1 = rotl32(x1, 6);  x1 ^= x0;
  x0 += ks2; x1 += ks0 + 5u;
  *o0 = x0; *o1 = x1;
}

// key for step t:  keys = jax.random.split(key(1), 48) -> keys[t]
__device__ __forceinline__ void step_key(int t, unsigned* k0, unsigned* k1) {
#if JAX_PARTITIONABLE
  threefry2x32(0u, 1u, 0u, (unsigned)t, k0, k1);
#else
  unsigned y0, y1;
  unsigned j0 = (unsigned)(2 * t), j1 = (unsigned)(2 * t + 1);
  if (j0 < 48u) { threefry2x32(0u, 1u, j0, j0 + 48u, &y0, &y1); *k0 = y0; }
  else          { threefry2x32(0u, 1u, j0 - 48u, j0, &y0, &y1); *k0 = y1; }
  if (j1 < 48u) { threefry2x32(0u, 1u, j1, j1 + 48u, &y0, &y1); *k1 = y0; }
  else          { threefry2x32(0u, 1u, j1 - 48u, j1, &y0, &y1); *k1 = y1; }
#endif
}

// random_bits(key, 32, (1,8))
__device__ __forceinline__ void step_bits(unsigned k0, unsigned k1, unsigned bits[8]) {
#if JAX_PARTITIONABLE
#pragma unroll
  for (int i = 0; i < 8; i++) {
    unsigned a, b;
    threefry2x32(k0, k1, 0u, (unsigned)i, &a, &b);
    bits[i] = a ^ b;
  }
#else
#pragma unroll
  for (int j = 0; j < 4; j++) {
    unsigned a, b;
    threefry2x32(k0, k1, (unsigned)j, (unsigned)(j + 4), &a, &b);
    bits[j] = a; bits[j + 4] = b;
  }
#endif
}

// ------------------------- math helpers -------------------------------------
__device__ __forceinline__ float sigm(float x) { return 1.0f / (1.0f + expf(-x)); }

// dot of 4 gate rows (u, u+2048, u+4096, u+6144) of W [8192 x 2048] with hv[2048]
__device__ __forceinline__ void warp_dot4(const float* __restrict__ W, int u,
                                          const float* __restrict__ hv,
                                          int lane, float acc[4]) {
  const float4* __restrict__ w0 = (const float4*)(W + (size_t)u * HD);
  const float4* __restrict__ w1 = (const float4*)(W + (size_t)(u + 2048) * HD);
  const float4* __restrict__ w2 = (const float4*)(W + (size_t)(u + 4096) * HD);
  const float4* __restrict__ w3 = (const float4*)(W + (size_t)(u + 6144) * HD);
  const float4* __restrict__ h4 = (const float4*)hv;
  float a0 = 0.f, a1 = 0.f, a2 = 0.f, a3 = 0.f;
#pragma unroll 2
  for (int i = lane; i < HD / 4; i += 32) {
    float4 h = h4[i];
    float4 p0 = w0[i], p1 = w1[i], p2 = w2[i], p3 = w3[i];
    a0 += p0.x * h.x + p0.y * h.y + p0.z * h.z + p0.w * h.w;
    a1 += p1.x * h.x + p1.y * h.y + p1.z * h.z + p1.w * h.w;
    a2 += p2.x * h.x + p2.y * h.y + p2.z * h.z + p2.w * h.w;
    a3 += p3.x * h.x + p3.y * h.y + p3.z * h.z + p3.w * h.w;
  }
#pragma unroll
  for (int off = 16; off; off >>= 1) {
    a0 += __shfl_xor_sync(0xffffffffu, a0, off);
    a1 += __shfl_xor_sync(0xffffffffu, a1, off);
    a2 += __shfl_xor_sync(0xffffffffu, a2, off);
    a3 += __shfl_xor_sync(0xffffffffu, a3, off);
  }
  acc[0] = a0; acc[1] = a1; acc[2] = a2; acc[3] = a3;
}

// ------------------------- main persistent kernel ---------------------------
__global__ void __launch_bounds__(NTH, 1)
nas_lstm_kernel(const float* __restrict__ emb,
                const float* __restrict__ Wih1, const float* __restrict__ Whh1,
                const float* __restrict__ bih1, const float* __restrict__ bhh1,
                const float* __restrict__ Wih2, const float* __restrict__ Whh2,
                const float* __restrict__ bih2, const float* __restrict__ bhh2,
                const float* __restrict__ Wout, const float* __restrict__ bout,
                float* __restrict__ out) {
  __shared__ __align__(16) float sA[HD];   // h1 staging
  __shared__ __align__(16) float sB[HD];   // h2 staging
  __shared__ int s_arow;                   // P1 row (offset+ind) of last action, -1 at t=0

  const int tid  = threadIdx.x;
  const int b    = blockIdx.x;
  const int w    = tid >> 5;
  const int lane = tid & 31;
  const int nblk = gridDim.x;
  const int TOTW = nblk * NWARPS;
  const int tau  = w * nblk + b;           // global warp-task id

  // ---- init: zero mutable state (block 0), precompute P1 (all warps) ----
  if (b == 0) {
    for (int i = tid; i < HD; i += NTH) {
      g_h1[i] = 0.f; g_h2[i] = 0.f; g_c1[i] = 0.f; g_c2[i] = 0.f;
    }
  }
  for (int r = tau; r < H4; r += TOTW) {
    float wreg[16];
    const float* wrow = Wih1 + (size_t)r * ED;
#pragma unroll
    for (int i = 0; i < 16; i++) wreg[i] = wrow[lane + i * 32];
    for (int m = 0; m < NEMB; m++) {
      const float* er = emb + m * ED;
      float p = 0.f;
#pragma unroll
      for (int i = 0; i < 16; i++) p += wreg[i] * er[lane + i * 32];
#pragma unroll
      for (int off = 16; off; off >>= 1) p += __shfl_xor_sync(0xffffffffu, p, off);
      if (lane == 0) g_P1[m * H4 + r] = p;
    }
  }
  grid_sync();

  // initial staging (zeros) + action sentinel
  for (int i = tid; i < HD; i += NTH) {
    sA[i] = __ldcg(&g_h1[i]);
    sB[i] = __ldcg(&g_h2[i]);
  }
  if (tid == 0) s_arow = -1;
  __syncthreads();

  const int sizes[4] = {8, 6, 4, 5};
  const int offs[4]  = {0, 8, 14, 18};

  for (int t = 0; t < TT; t++) {
    const int arow = s_arow;
    float acc[4];

    // ---------------- phase 1: W_hh1*h1_prev and W_hh2*h2_prev -------------
    for (int r = tau; r < 4096; r += TOTW) {
      const bool l2 = (r >= 2048);
      const int  u  = r & (HD - 1);
      warp_dot4(l2 ? Whh2 : Whh1, u, l2 ? sB : sA, lane, acc);
      if (l2) {
        if (lane == 0) {
          g_w2[u]        = acc[0];
          g_w2[u + 2048] = acc[1];
          g_w2[u + 4096] = acc[2];
          g_w2[u + 6144] = acc[3];
        }
      } else if (lane == 0) {
        float gi = acc[0] + bih1[u]        + bhh1[u];
        float gf = acc[1] + bih1[u + 2048] + bhh1[u + 2048];
        float gg = acc[2] + bih1[u + 4096] + bhh1[u + 4096];
        float go = acc[3] + bih1[u + 6144] + bhh1[u + 6144];
        if (arow >= 0) {
          const float* P = g_P1 + (size_t)arow * H4 + u;
          gi += P[0]; gf += P[2048]; gg += P[4096]; go += P[6144];
        }
        float c = sigm(gf) * g_c1[u] + sigm(gi) * tanhf(gg);
        g_c1[u] = c;
        g_h1[u] = sigm(go) * tanhf(c);
      }
    }
    grid_sync();

    // restage h1 (new)
    for (int i = tid; i < HD; i += NTH) sA[i] = __ldcg(&g_h1[i]);
    __syncthreads();

    // ---------------- phase 2: W_ih2*h1_new + stashed hh gates -------------
    for (int u = tau; u < HD; u += TOTW) {
      warp_dot4(Wih2, u, sA, lane, acc);
      if (lane == 0) {
        float gi = acc[0] + __ldcg(&g_w2[u])        + bih2[u]        + bhh2[u];
        float gf = acc[1] + __ldcg(&g_w2[u + 2048]) + bih2[u + 2048] + bhh2[u + 2048];
        float gg = acc[2] + __ldcg(&g_w2[u + 4096]) + bih2[u + 4096] + bhh2[u + 4096];
        float go = acc[3] + __ldcg(&g_w2[u + 6144]) + bih2[u + 6144] + bhh2[u + 6144];
        float c = sigm(gf) * g_c2[u] + sigm(gi) * tanhf(gg);
        g_c2[u] = c;
        g_h2[u] = sigm(go) * tanhf(c);
      }
    }
    grid_sync();

    // restage h2 (new) — also the sampling input
    for (int i = tid; i < HD; i += NTH) sB[i] = __ldcg(&g_h2[i]);
    __syncthreads();

    // ---------------- sampling: redundant per block (warp 0) ---------------
    if (w == 0) {
      const float4* h4 = (const float4*)sB;
      float lg[8];
#pragma unroll
      for (int j = 0; j < 8; j++) {
        const float4* wr = (const float4*)(Wout + ((size_t)t * MAXS + j) * HD);
        float p = 0.f;
        for (int i = lane; i < HD / 4; i += 32) {
          float4 a = wr[i]; float4 h = h4[i];
          p += a.x * h.x + a.y * h.y + a.z * h.z + a.w * h.w;
        }
#pragma unroll
        for (int off = 16; off; off >>= 1) p += __shfl_xor_sync(0xffffffffu, p, off);
        lg[j] = p + bout[t * MAXS + j];
      }
      if (lane == 0) {
        const int tp = t & 3;
        const int sz = sizes[tp];
        float l[8];
#pragma unroll
        for (int j = 0; j < 8; j++) l[j] = (j < sz) ? lg[j] : -1e9f;

        unsigned k0, k1, bits[8];
        step_key(t, &k0, &k1);
        step_bits(k0, k1, bits);

        float gmb[8];
#pragma unroll
        for (int j = 0; j < 8; j++) {
          unsigned fb = (bits[j] >> 9) | 0x3f800000u;
          float uu = __uint_as_float(fb) - 1.0f;     // [0,1)
          uu = fmaxf(TINYF, uu + TINYF);             // jax.random.uniform exact
          gmb[j] = -logf(-logf(uu));
        }
        int   best = 0;
        float bv   = l[0] + gmb[0];
#pragma unroll
        for (int j = 1; j < 8; j++) {
          float v = l[j] + gmb[j];
          if (v > bv) { bv = v; best = j; }          // first-max like jnp.argmax
        }
        float m = l[0];
#pragma unroll
        for (int j = 1; j < 8; j++) m = fmaxf(m, l[j]);
        float s = 0.f;
#pragma unroll
        for (int j = 0; j < 8; j++) s += expf(l[j] - m);
        float prob = expf(l[best] - m) / s;

        s_arow = offs[tp] + best;                    // next embedding / P1 row
        if (b == 0) {
          out[t]      = (float)best;                 // actions (int -> float exact)
          out[TT + t] = prob;                        // action_probs
        }
      }
    }
    __syncthreads();   // publish s_arow; sA holds h1_t, sB holds h2_t
  }
}

// ------------------------- launch -------------------------------------------
extern "C" void kernel_launch(void* const* d_in, const int* in_sizes, int n_in,
                              void* d_out, int out_size) {
  const float* emb  = (const float*)d_in[0];
  const float* Wih1 = (const float*)d_in[1];
  const float* Whh1 = (const float*)d_in[2];
  const float* bih1 = (const float*)d_in[3];
  const float* bhh1 = (const float*)d_in[4];
  const float* Wih2 = (const float*)d_in[5];
  const float* Whh2 = (const float*)d_in[6];
  const float* bih2 = (const float*)d_in[7];
  const float* bhh2 = (const float*)d_in[8];
  const float* Wout = (const float*)d_in[9];
  const float* bout = (const float*)d_in[10];
  (void)in_sizes; (void)n_in; (void)out_size;

  // Deadlock-proof grid sizing: never exceed guaranteed co-residency.
  int dev = 0;
  cudaGetDevice(&dev);
  int sms = 0;
  cudaDeviceGetAttribute(&sms, cudaDevAttrMultiProcessorCount, dev);
  int occ = 0;
  cudaOccupancyMaxActiveBlocksPerMultiprocessor(&occ, nas_lstm_kernel, NTH, 0);
  if (occ < 1) occ = 1;              // defensive; launch would fail anyway
  int nblk = sms * occ;
  if (nblk > 1024) nblk = 1024;      // tau mapping headroom
  if (nblk < 1) nblk = 1;

  nas_lstm_kernel<<<nblk, NTH>>>(emb, Wih1, Whh1, bih1, bhh1,
                                 Wih2, Whh2, bih2, bhh2,
                                 Wout, bout, (float*)d_out);
}

// round 3
// speedup vs baseline: 1.0968x; 1.0968x over previous
#include <cuda_runtime.h>
#include <math.h>
#include <stdint.h>

// ---------------------------------------------------------------------------
// NAS-controller LSTM, persistent kernel v3.
//  - block-cooperative cp.async.bulk weight streaming (double-buffered 64KB
//    chunks, mbarrier completion)  -> saturate DRAM regardless of reg budget
//  - per step: phaseA = Whh1 dots (64MB), phaseB = Whh2 + Wih2 dots (128MB)
//  - activations + cell state computed REDUNDANTLY per block in smem
//    (no global h/c exchange, no restage passes), 2 grid barriers / step
//  - sampling: 8 parallel warps for logits, thread-0 finalize
//  - threefry2x32 partitionable path (verified bit-exact in round 2)
// ---------------------------------------------------------------------------

#define HD    2048
#define H4    8192
#define ED    512
#define TT    48
#define MAXS  8
#define NEMB  23
#define NTH   1024
#define NWARPS 32
#define TINYF 1.17549435e-38f

// streaming geometry
#define RPT   32                 // rows per tile
#define KCH   512                // floats per K-chunk
#define NKCH  4                  // 2048 / 512
#define CHUNK_BYTES (RPT * KCH * 4)   // 65536

// dynamic smem layout (bytes)
#define OFF_BUF   0
#define OFF_SA    (2 * CHUNK_BYTES)          // 131072  h1 (float[2048])
#define OFF_SB    (OFF_SA + HD * 4)          // h2
#define OFF_SC1   (OFF_SB + HD * 4)          // c1
#define OFF_SC2   (OFF_SC1 + HD * 4)         // c2
#define OFF_BAR   (OFF_SC2 + HD * 4)         // 2 mbarriers (16B)
#define OFF_LG    (OFF_BAR + 16)             // 8 logits
#define OFF_AROW  (OFF_LG + 32)
#define SMEM_TOTAL (OFF_AROW + 16)           // 163904

// ------------------------- device scratch ----------------------------------
__device__ float    g_P1[NEMB * H4];
__device__ float    g_dot1[H4];   // Whh1 . h1
__device__ float    g_dot2[H4];   // Whh2 . h2
__device__ float    g_dot3[H4];   // Wih2 . h1new
__device__ float    g_b1[H4];     // bih1 + bhh1
__device__ float    g_b2[H4];     // bih2 + bhh2
__device__ unsigned g_count = 0;
__device__ unsigned g_gen   = 0;

// ------------------------- grid barrier ------------------------------------
__device__ __forceinline__ void grid_sync() {
  __threadfence();
  __syncthreads();
  if (threadIdx.x == 0) {
    volatile unsigned* vg = (volatile unsigned*)&g_gen;
    unsigned gen = *vg;
    __threadfence();
    if (atomicAdd(&g_count, 1u) == (unsigned)(gridDim.x - 1)) {
      g_count = 0u;
      __threadfence();
      atomicAdd(&g_gen, 1u);
    } else {
      while (*vg == gen) { __nanosleep(64); }
    }
  }
  __syncthreads();
}

// ------------------------- mbarrier / bulk copy -----------------------------
__device__ __forceinline__ uint32_t smem_u32(const void* p) {
  uint32_t a;
  asm("{ .reg .u64 t; cvta.to.shared.u64 t, %1; cvt.u32.u64 %0, t; }"
      : "=r"(a) : "l"(p));
  return a;
}
__device__ __forceinline__ void mbar_init(uint32_t a, uint32_t cnt) {
  asm volatile("mbarrier.init.shared.b64 [%0], %1;" :: "r"(a), "r"(cnt) : "memory");
}
__device__ __forceinline__ void mbar_expect(uint32_t a, uint32_t tx) {
  asm volatile("mbarrier.arrive.expect_tx.shared.b64 _, [%0], %1;"
               :: "r"(a), "r"(tx) : "memory");
}
__device__ __forceinline__ void mbar_wait(uint32_t a, unsigned ph) {
  asm volatile(
      "{\n\t.reg .pred P;\n"
      "W%=:\n\t"
      "mbarrier.try_wait.parity.shared.b64 P, [%0], %1;\n\t"
      "@P bra D%=;\n\t"
      "bra W%=;\n"
      "D%=:\n\t}"
      :: "r"(a), "r"(ph) : "memory");
}
__device__ __forceinline__ void bulk_g2s(uint32_t dst, const float* src,
                                         uint32_t bytes, uint32_t bar) {
  asm volatile(
      "cp.async.bulk.shared::cluster.global.mbarrier::complete_tx::bytes "
      "[%0], [%1], %2, [%3];"
      :: "r"(dst), "l"(src), "r"(bytes), "r"(bar) : "memory");
}

// ------------------------- threefry2x32 (verified exact) --------------------
__device__ __forceinline__ unsigned rotl32(unsigned x, int r) {
  return (x << r) | (x >> (32 - r));
}
__device__ __forceinline__ void threefry2x32(unsigned k0, unsigned k1,
                                             unsigned x0, unsigned x1,
                                             unsigned* o0, unsigned* o1) {
  unsigned ks0 = k0, ks1 = k1, ks2 = k0 ^ k1 ^ 0x1BD11BDAu;
  x0 += ks0; x1 += ks1;
  x0 += x1; x1 = rotl32(x1, 13); x1 ^= x0;
  x0 += x1; x1 = rotl32(x1, 15); x1 ^= x0;
  x0 += x1; x1 = rotl32(x1, 26); x1 ^= x0;
  x0 += x1; x1 = rotl32(x1, 6);  x1 ^= x0;
  x0 += ks1; x1 += ks2 + 1u;
  x0 += x1; x1 = rotl32(x1, 17); x1 ^= x0;
  x0 += x1; x1 = rotl32(x1, 29); x1 ^= x0;
  x0 += x1; x1 = rotl32(x1, 16); x1 ^= x0;
  x0 += x1; x1 = rotl32(x1, 24); x1 ^= x0;
  x0 += ks2; x1 += ks0 + 2u;
  x0 += x1; x1 = rotl32(x1, 13); x1 ^= x0;
  x0 += x1; x1 = rotl32(x1, 15); x1 ^= x0;
  x0 += x1; x1 = rotl32(x1, 26); x1 ^= x0;
  x0 += x1; x1 = rotl32(x1, 6);  x1 ^= x0;
  x0 += ks0; x1 += ks1 + 3u;
  x0 += x1; x1 = rotl32(x1, 17); x1 ^= x0;
  x0 += x1; x1 = rotl32(x1, 29); x1 ^= x0;
  x0 += x1; x1 = rotl32(x1, 16); x1 ^= x0;
  x0 += x1; x1 = rotl32(x1, 24); x1 ^= x0;
  x0 += ks1; x1 += ks2 + 4u;
  x0 += x1; x1 = rotl32(x1, 13); x1 ^= x0;
  x0 += x1; x1 = rotl32(x1, 15); x1 ^= x0;
  x0 += x1; x1 = rotl32(x1, 26); x1 ^= x0;
  x0 += x1; x1 = rotl32(x1, 6);  x1 ^= x0;
  x0 += ks2; x1 += ks0 + 5u;
  *o0 = x0; *o1 = x1;
}
__device__ __forceinline__ void step_key(int t, unsigned* k0, unsigned* k1) {
  threefry2x32(0u, 1u, 0u, (unsigned)t, k0, k1);
}
__device__ __forceinline__ void step_bits(unsigned k0, unsigned k1, unsigned bits[8]) {
#pragma unroll
  for (int i = 0; i < 8; i++) {
    unsigned a, b;
    threefry2x32(k0, k1, 0u, (unsigned)i, &a, &b);
    bits[i] = a ^ b;
  }
}

__device__ __forceinline__ float sigm(float x) { return 1.0f / (1.0f + expf(-x)); }

// resolve tile -> (W, rowbase, h smem offset, dst)
__device__ __forceinline__ void resolve_tile(
    int isB, int tile,
    const float* __restrict__ Whh1, const float* __restrict__ Whh2,
    const float* __restrict__ Wih2,
    const float** W, int* rowbase, int* hoff, float** dst) {
  if (!isB) {                       // phase A: Whh1 vs h1_prev
    *W = Whh1; *rowbase = tile * RPT; *hoff = OFF_SA; *dst = g_dot1;
  } else if (tile < 256) {          // phase B: Whh2 vs h2_prev
    *W = Whh2; *rowbase = tile * RPT; *hoff = OFF_SB; *dst = g_dot2;
  } else {                          // phase B: Wih2 vs h1_new
    *W = Wih2; *rowbase = (tile - 256) * RPT; *hoff = OFF_SA; *dst = g_dot3;
  }
}

// streaming dot phase: NT tiles, grid-strided across blocks, double-buffered.
__device__ __forceinline__ void run_phase(
    int NT, int isB,
    const float* __restrict__ Whh1, const float* __restrict__ Whh2,
    const float* __restrict__ Wih2,
    char* sm, uint32_t smu, int b, int nblk,
    int w, int lane, int tid, unsigned ph[2]) {
  const int ntiles = (b < NT) ? ((NT - 1 - b) / nblk + 1) : 0;
  const int CH = ntiles * NKCH;
  const uint32_t bars[2] = {smu + OFF_BAR, smu + OFF_BAR + 8};

  // prologue: issue chunks 0,1
#pragma unroll
  for (int p = 0; p < 2; p++) {
    if (p < CH) {
      if (tid == 0) mbar_expect(bars[p], CHUNK_BYTES);
      const int tile = b;                  // p>>2 == 0
      const int kc = p;
      const float* W; int rowbase, hoff; float* dst;
      resolve_tile(isB, tile, Whh1, Whh2, Wih2, &W, &rowbase, &hoff, &dst);
      if (lane == 0)
        bulk_g2s(smu + OFF_BUF + (uint32_t)p * CHUNK_BYTES + (uint32_t)w * 2048,
                 W + (size_t)(rowbase + w) * HD + (size_t)kc * KCH,
                 2048u, bars[p]);
    }
  }

  float acc = 0.f;
  for (int c = 0; c < CH; c++) {
    const int bi = c & 1;
    mbar_wait(bars[bi], ph[bi]); ph[bi] ^= 1u;

    const int tile = b + (c >> 2) * nblk;
    const int kc = c & 3;
    const float* W; int rowbase, hoff; float* dst;
    resolve_tile(isB, tile, Whh1, Whh2, Wih2, &W, &rowbase, &hoff, &dst);

    const float4* bw = (const float4*)(sm + OFF_BUF + bi * CHUNK_BYTES) + w * 128;
    const float4* hp = (const float4*)(sm + hoff) + kc * 128;
#pragma unroll
    for (int i = 0; i < 4; i++) {
      const int j = lane + i * 32;
      float4 a = bw[j], h = hp[j];
      acc += a.x * h.x + a.y * h.y + a.z * h.z + a.w * h.w;
    }
    if (kc == 3) {
      float r = acc;
#pragma unroll
      for (int off = 16; off; off >>= 1) r += __shfl_xor_sync(0xffffffffu, r, off);
      if (lane == 0) __stcg(&dst[rowbase + w], r);
      acc = 0.f;
    }
    __syncthreads();   // whole block done with buffer bi -> safe to reissue

    const int cn = c + 2;
    if (cn < CH) {
      if (tid == 0) mbar_expect(bars[bi], CHUNK_BYTES);
      const int tile2 = b + (cn >> 2) * nblk;
      const int kc2 = cn & 3;
      const float* W2; int rb2, ho2; float* d2;
      resolve_tile(isB, tile2, Whh1, Whh2, Wih2, &W2, &rb2, &ho2, &d2);
      if (lane == 0)
        bulk_g2s(smu + OFF_BUF + (uint32_t)bi * CHUNK_BYTES + (uint32_t)w * 2048,
                 W2 + (size_t)(rb2 + w) * HD + (size_t)kc2 * KCH,
                 2048u, bars[bi]);
    }
  }
}

// ------------------------- main persistent kernel ---------------------------
__global__ void __launch_bounds__(NTH, 1)
nas_lstm_kernel(const float* __restrict__ emb,
                const float* __restrict__ Wih1, const float* __restrict__ Whh1,
                const float* __restrict__ bih1, const float* __restrict__ bhh1,
                const float* __restrict__ Wih2, const float* __restrict__ Whh2,
                const float* __restrict__ bih2, const float* __restrict__ bhh2,
                const float* __restrict__ Wout, const float* __restrict__ bout,
                float* __restrict__ out) {
  extern __shared__ __align__(16) char sm[];
  const uint32_t smu = smem_u32(sm);

  const int tid  = threadIdx.x;
  const int b    = blockIdx.x;
  const int w    = tid >> 5;
  const int lane = tid & 31;
  const int nblk = gridDim.x;

  float* sA  = (float*)(sm + OFF_SA);
  float* sB  = (float*)(sm + OFF_SB);
  float* sC1 = (float*)(sm + OFF_SC1);
  float* sC2 = (float*)(sm + OFF_SC2);
  float* sLG = (float*)(sm + OFF_LG);
  int*   sAR = (int*)(sm + OFF_AROW);

  // ---------------- init ----------------
  for (int i = tid; i < HD; i += NTH) {
    sA[i] = 0.f; sB[i] = 0.f; sC1[i] = 0.f; sC2[i] = 0.f;
  }
  if (tid == 0) {
    mbar_init(smu + OFF_BAR, 1u);
    mbar_init(smu + OFF_BAR + 8, 1u);
    asm volatile("fence.proxy.async.shared::cta;" ::: "memory");
    *sAR = -1;
  }
  // combined biases (grid-strided, disjoint)
  for (int i = b * NTH + tid; i < H4; i += nblk * NTH) {
    g_b1[i] = bih1[i] + bhh1[i];
    g_b2[i] = bih2[i] + bhh2[i];
  }
  // P1 = emb @ Wih1^T  (warp per row)
  {
    const int TOTW = nblk * NWARPS;
    const int tau = w * nblk + b;
    for (int r = tau; r < H4; r += TOTW) {
      float wreg[16];
      const float* wrow = Wih1 + (size_t)r * ED;
#pragma unroll
      for (int i = 0; i < 16; i++) wreg[i] = wrow[lane + i * 32];
      for (int m = 0; m < NEMB; m++) {
        const float* er = emb + m * ED;
        float p = 0.f;
#pragma unroll
        for (int i = 0; i < 16; i++) p += wreg[i] * er[lane + i * 32];
#pragma unroll
        for (int off = 16; off; off >>= 1) p += __shfl_xor_sync(0xffffffffu, p, off);
        if (lane == 0) g_P1[m * H4 + r] = p;
      }
    }
  }
  grid_sync();

  unsigned ph[2] = {0u, 0u};
  const int sizes[4] = {8, 6, 4, 5};
  const int offs[4]  = {0, 8, 14, 18};

  for (int t = 0; t < TT; t++) {
    // -------- phase A: Whh1 . h1_prev  (256 tiles) --------
    run_phase(256, 0, Whh1, Whh2, Wih2, sm, smu, b, nblk, w, lane, tid, ph);
    grid_sync();

    // -------- mid: layer-1 activation (redundant per block) --------
    {
      const int arow = *sAR;
      for (int u = tid; u < HD; u += NTH) {
        float di = __ldcg(&g_dot1[u])        + __ldcg(&g_b1[u]);
        float df = __ldcg(&g_dot1[u + 2048]) + __ldcg(&g_b1[u + 2048]);
        float dg = __ldcg(&g_dot1[u + 4096]) + __ldcg(&g_b1[u + 4096]);
        float dz = __ldcg(&g_dot1[u + 6144]) + __ldcg(&g_b1[u + 6144]);
        if (arow >= 0) {
          const float* P = g_P1 + (size_t)arow * H4 + u;
          di += __ldcg(&P[0]);    df += __ldcg(&P[2048]);
          dg += __ldcg(&P[4096]); dz += __ldcg(&P[6144]);
        }
        float c = sigm(df) * sC1[u] + sigm(di) * tanhf(dg);
        sC1[u] = c;
        sA[u]  = sigm(dz) * tanhf(c);
      }
    }
    __syncthreads();

    // -------- phase B: Whh2 . h2_prev + Wih2 . h1_new (512 tiles) --------
    run_phase(512, 1, Whh1, Whh2, Wih2, sm, smu, b, nblk, w, lane, tid, ph);
    grid_sync();

    // -------- end: layer-2 activation (redundant per block) --------
    for (int u = tid; u < HD; u += NTH) {
      float di = __ldcg(&g_dot3[u])        + __ldcg(&g_dot2[u])        + __ldcg(&g_b2[u]);
      float df = __ldcg(&g_dot3[u + 2048]) + __ldcg(&g_dot2[u + 2048]) + __ldcg(&g_b2[u + 2048]);
      float dg = __ldcg(&g_dot3[u + 4096]) + __ldcg(&g_dot2[u + 4096]) + __ldcg(&g_b2[u + 4096]);
      float dz = __ldcg(&g_dot3[u + 6144]) + __ldcg(&g_dot2[u + 6144]) + __ldcg(&g_b2[u + 6144]);
      float c = sigm(df) * sC2[u] + sigm(di) * tanhf(dg);
      sC2[u] = c;
      sB[u]  = sigm(dz) * tanhf(c);
    }
    __syncthreads();

    // -------- logits (8 parallel warps) --------
    if (w < 8) {
      const float4* wr = (const float4*)(Wout + ((size_t)t * MAXS + w) * HD);
      const float4* h4 = (const float4*)sB;
      float p = 0.f;
#pragma unroll 4
      for (int i = lane; i < HD / 4; i += 32) {
        float4 a = wr[i], h = h4[i];
        p += a.x * h.x + a.y * h.y + a.z * h.z + a.w * h.w;
      }
#pragma unroll
      for (int off = 16; off; off >>= 1) p += __shfl_xor_sync(0xffffffffu, p, off);
      if (lane == 0) sLG[w] = p + bout[t * MAXS + w];
    }
    __syncthreads();

    // -------- finalize sample (thread 0) --------
    if (tid == 0) {
      const int tp = t & 3;
      const int sz = sizes[tp];
      float l[8];
#pragma unroll
      for (int j = 0; j < 8; j++) l[j] = (j < sz) ? sLG[j] : -1e9f;

      unsigned k0, k1, bits[8];
      step_key(t, &k0, &k1);
      step_bits(k0, k1, bits);

      float gmb[8];
#pragma unroll
      for (int j = 0; j < 8; j++) {
        unsigned fb = (bits[j] >> 9) | 0x3f800000u;
        float uu = __uint_as_float(fb) - 1.0f;
        uu = fmaxf(TINYF, uu + TINYF);
        gmb[j] = -logf(-logf(uu));
      }
      int best = 0;
      float bv = l[0] + gmb[0];
#pragma unroll
      for (int j = 1; j < 8; j++) {
        float v = l[j] + gmb[j];
        if (v > bv) { bv = v; best = j; }
      }
      float m = l[0];
#pragma unroll
      for (int j = 1; j < 8; j++) m = fmaxf(m, l[j]);
      float s = 0.f;
#pragma unroll
      for (int j = 0; j < 8; j++) s += expf(l[j] - m);
      float prob = expf(l[best] - m) / s;

      *sAR = offs[tp] + best;
      if (b == 0) {
        out[t]      = (float)best;
        out[TT + t] = prob;
      }
    }
    __syncthreads();
  }
}

// ------------------------- launch -------------------------------------------
extern "C" void kernel_launch(void* const* d_in, const int* in_sizes, int n_in,
                              void* d_out, int out_size) {
  const float* emb  = (const float*)d_in[0];
  const float* Wih1 = (const float*)d_in[1];
  const float* Whh1 = (const float*)d_in[2];
  const float* bih1 = (const float*)d_in[3];
  const float* bhh1 = (const float*)d_in[4];
  const float* Wih2 = (const float*)d_in[5];
  const float* Whh2 = (const float*)d_in[6];
  const float* bih2 = (const float*)d_in[7];
  const float* bhh2 = (const float*)d_in[8];
  const float* Wout = (const float*)d_in[9];
  const float* bout = (const float*)d_in[10];
  (void)in_sizes; (void)n_in; (void)out_size;

  static int configured = 0;
  if (!configured) {
    cudaFuncSetAttribute(nas_lstm_kernel,
                         cudaFuncAttributeMaxDynamicSharedMemorySize, SMEM_TOTAL);
    configured = 1;
  }

  int dev = 0;
  cudaGetDevice(&dev);
  int sms = 0;
  cudaDeviceGetAttribute(&sms, cudaDevAttrMultiProcessorCount, dev);
  int occ = 0;
  cudaOccupancyMaxActiveBlocksPerMultiprocessor(&occ, nas_lstm_kernel, NTH,
                                                SMEM_TOTAL);
  if (occ < 1) occ = 1;
  int nblk = sms * occ;
  if (nblk > 128) nblk = 128;   // 128 divides the tile counts exactly
  if (nblk < 1) nblk = 1;

  nas_lstm_kernel<<<nblk, NTH, SMEM_TOTAL>>>(emb, Wih1, Whh1, bih1, bhh1,
                                             Wih2, Whh2, bih2, bhh2,
                                             Wout, bout, (float*)d_out);
}

// round 4
// speedup vs baseline: 1.1822x; 1.0778x over previous
#include <cuda_runtime.h>
#include <math.h>
#include <stdint.h>

// ---------------------------------------------------------------------------
// NAS-controller LSTM, persistent kernel v4.
//  - per-WARP independent TMA rings (3 x 2KB slices, private mbarriers):
//    no block syncs in the stream loop, issue-ahead crosses phase boundaries
//    and grid barriers  -> latency fully hidden, smooth DRAM request flow
//  - step: [stream Whh1+Whh2] sync [act1] [stream Wih2] sync [act2+logits+sample]
//  - bias + P1(action) folded into streamed row stores; cells in registers
//  - g_dot2 double-buffered by step parity (breaks cross-step race)
//  - threefry2x32 partitionable path (verified bit-exact)
// ---------------------------------------------------------------------------

#define HD    2048
#define H4    8192
#define ED    512
#define TT    48
#define MAXS  8
#define NEMB  23
#define NTH   1024
#define NWARPS 32
#define TINYF 1.17549435e-38f

#define NS    3                   // ring slots per warp
#define SLICE 2048                // bytes per slice (512 floats)
#define KCH   512                 // floats per K-chunk

// smem layout (bytes)
#define OFF_SA    0
#define OFF_SB    8192
#define OFF_LG    16384
#define OFF_AROW  16416
#define OFF_MBAR  16432                      // 32*3*8 = 768
#define OFF_RING  17408                      // 32*3*2048 = 196608
#define SMEM_TOTAL (OFF_RING + NWARPS * NS * SLICE)   // 214016

// ------------------------- device scratch ----------------------------------
__device__ float    g_P1[NEMB * H4];
__device__ float    g_dot1[H4];        // Whh1.h1 (+bias+P1)
__device__ float    g_dot2[2 * H4];    // Whh2.h2, step-parity double buffered
__device__ float    g_dot3[H4];        // Wih2.h1new (+bias)
__device__ float    g_b1[H4];          // bih1+bhh1
__device__ float    g_b2[H4];          // bih2+bhh2
__device__ unsigned g_count = 0;
__device__ unsigned g_gen   = 0;

// ------------------------- grid barrier ------------------------------------
__device__ __forceinline__ void grid_sync() {
  __threadfence();
  __syncthreads();
  if (threadIdx.x == 0) {
    volatile unsigned* vg = (volatile unsigned*)&g_gen;
    unsigned gen = *vg;
    __threadfence();
    if (atomicAdd(&g_count, 1u) == (unsigned)(gridDim.x - 1)) {
      g_count = 0u;
      __threadfence();
      atomicAdd(&g_gen, 1u);
    } else {
      while (*vg == gen) { __nanosleep(32); }
    }
  }
  __syncthreads();
}

// ------------------------- mbarrier / bulk copy -----------------------------
__device__ __forceinline__ uint32_t smem_u32(const void* p) {
  uint32_t a;
  asm("{ .reg .u64 t; cvta.to.shared.u64 t, %1; cvt.u32.u64 %0, t; }"
      : "=r"(a) : "l"(p));
  return a;
}
__device__ __forceinline__ void mbar_init(uint32_t a, uint32_t cnt) {
  asm volatile("mbarrier.init.shared.b64 [%0], %1;" :: "r"(a), "r"(cnt) : "memory");
}
__device__ __forceinline__ void mbar_expect(uint32_t a, uint32_t tx) {
  asm volatile("mbarrier.arrive.expect_tx.shared.b64 _, [%0], %1;"
               :: "r"(a), "r"(tx) : "memory");
}
__device__ __forceinline__ void mbar_wait(uint32_t a, unsigned ph) {
  asm volatile(
      "{\n\t.reg .pred P;\n"
      "W%=:\n\t"
      "mbarrier.try_wait.parity.shared.b64 P, [%0], %1;\n\t"
      "@P bra D%=;\n\t"
      "bra W%=;\n"
      "D%=:\n\t}"
      :: "r"(a), "r"(ph) : "memory");
}
__device__ __forceinline__ void bulk_g2s(uint32_t dst, const float* src,
                                         uint32_t bytes, uint32_t bar) {
  asm volatile(
      "cp.async.bulk.shared::cluster.global.mbarrier::complete_tx::bytes "
      "[%0], [%1], %2, [%3];"
      :: "r"(dst), "l"(src), "r"(bytes), "r"(bar) : "memory");
}

// ------------------------- threefry2x32 (verified exact) --------------------
__device__ __forceinline__ unsigned rotl32(unsigned x, int r) {
  return (x << r) | (x >> (32 - r));
}
__device__ __forceinline__ void threefry2x32(unsigned k0, unsigned k1,
                                             unsigned x0, unsigned x1,
                                             unsigned* o0, unsigned* o1) {
  unsigned ks0 = k0, ks1 = k1, ks2 = k0 ^ k1 ^ 0x1BD11BDAu;
  x0 += ks0; x1 += ks1;
  x0 += x1; x1 = rotl32(x1, 13); x1 ^= x0;
  x0 += x1; x1 = rotl32(x1, 15); x1 ^= x0;
  x0 += x1; x1 = rotl32(x1, 26); x1 ^= x0;
  x0 += x1; x1 = rotl32(x1, 6);  x1 ^= x0;
  x0 += ks1; x1 += ks2 + 1u;
  x0 += x1; x1 = rotl32(x1, 17); x1 ^= x0;
  x0 += x1; x1 = rotl32(x1, 29); x1 ^= x0;
  x0 += x1; x1 = rotl32(x1, 16); x1 ^= x0;
  x0 += x1; x1 = rotl32(x1, 24); x1 ^= x0;
  x0 += ks2; x1 += ks0 + 2u;
  x0 += x1; x1 = rotl32(x1, 13); x1 ^= x0;
  x0 += x1; x1 = rotl32(x1, 15); x1 ^= x0;
  x0 += x1; x1 = rotl32(x1, 26); x1 ^= x0;
  x0 += x1; x1 = rotl32(x1, 6);  x1 ^= x0;
  x0 += ks0; x1 += ks1 + 3u;
  x0 += x1; x1 = rotl32(x1, 17); x1 ^= x0;
  x0 += x1; x1 = rotl32(x1, 29); x1 ^= x0;
  x0 += x1; x1 = rotl32(x1, 16); x1 ^= x0;
  x0 += x1; x1 = rotl32(x1, 24); x1 ^= x0;
  x0 += ks1; x1 += ks2 + 4u;
  x0 += x1; x1 = rotl32(x1, 13); x1 ^= x0;
  x0 += x1; x1 = rotl32(x1, 15); x1 ^= x0;
  x0 += x1; x1 = rotl32(x1, 26); x1 ^= x0;
  x0 += x1; x1 = rotl32(x1, 6);  x1 ^= x0;
  x0 += ks2; x1 += ks0 + 5u;
  *o0 = x0; *o1 = x1;
}

__device__ __forceinline__ float sigm(float x) { return 1.0f / (1.0f + expf(-x)); }

// ------------------------- stream helpers -----------------------------------
// slice index m within a step: [0,nsl)=Whh1, [nsl,2nsl)=Whh2, [2nsl,3nsl)=Wih2
__device__ __forceinline__ void issue_slice(
    int iss, int nsl, int wg, int totw,
    const float* __restrict__ Whh1, const float* __restrict__ Whh2,
    const float* __restrict__ Wih2,
    uint32_t ring, uint32_t bar) {
  const int slot = iss % NS;
  const int m = iss % (3 * nsl);
  const float* W; int s;
  if (m < nsl)            { W = Whh1; s = m; }
  else if (m < 2 * nsl)   { W = Whh2; s = m - nsl; }
  else                    { W = Wih2; s = m - 2 * nsl; }
  const int row = wg + (s >> 2) * totw;
  const int kc = s & 3;
  const uint32_t ba = bar + slot * 8;
  mbar_expect(ba, SLICE);
  bulk_g2s(ring + slot * SLICE, W + (size_t)row * HD + kc * KCH, SLICE, ba);
}

__device__ __forceinline__ void consume_slice(
    int con, int nsl, int wg, int totw, const char* sm,
    uint32_t bar, int ringoff, float* __restrict__ dot2cur, int arow,
    int lane, unsigned* ph, float* acc) {
  const int slot = con % NS;
  const int m = con % (3 * nsl);
  mbar_wait(bar + slot * 8, (*ph >> slot) & 1u);
  *ph ^= (1u << slot);

  const float* hv; float* dst; int s, segk;
  if (m < nsl)          { hv = (const float*)(sm + OFF_SA); dst = g_dot1;  s = m;           segk = 0; }
  else if (m < 2 * nsl) { hv = (const float*)(sm + OFF_SB); dst = dot2cur; s = m - nsl;     segk = 1; }
  else                  { hv = (const float*)(sm + OFF_SA); dst = g_dot3;  s = m - 2 * nsl; segk = 2; }
  const int row = wg + (s >> 2) * totw;
  const int kc = s & 3;

  const float4* wp = (const float4*)(sm + ringoff + slot * SLICE);
  const float4* hp = (const float4*)hv + kc * 128;
  float a = *acc;
#pragma unroll
  for (int i = 0; i < 4; i++) {
    const int j = lane + i * 32;
    float4 x = wp[j], h = hp[j];
    a += x.x * h.x + x.y * h.y + x.z * h.z + x.w * h.w;
  }
  if (kc == 3) {
#pragma unroll
    for (int off = 16; off; off >>= 1) a += __shfl_xor_sync(0xffffffffu, a, off);
    if (lane == 0) {
      float extra = 0.f;
      if (segk == 0) {
        extra = __ldcg(&g_b1[row]);
        if (arow >= 0) extra += __ldcg(&g_P1[(size_t)arow * H4 + row]);
      } else if (segk == 2) {
        extra = __ldcg(&g_b2[row]);
      }
      __stcg(&dst[row], a + extra);
    }
    a = 0.f;
  }
  *acc = a;
}

// ------------------------- main persistent kernel ---------------------------
__global__ void __launch_bounds__(NTH, 1)
nas_lstm_kernel(const float* __restrict__ emb,
                const float* __restrict__ Wih1, const float* __restrict__ Whh1,
                const float* __restrict__ bih1, const float* __restrict__ bhh1,
                const float* __restrict__ Wih2, const float* __restrict__ Whh2,
                const float* __restrict__ bih2, const float* __restrict__ bhh2,
                const float* __restrict__ Wout, const float* __restrict__ bout,
                float* __restrict__ out) {
  extern __shared__ __align__(16) char sm[];
  const uint32_t smu = smem_u32(sm);

  const int tid  = threadIdx.x;
  const int b    = blockIdx.x;
  const int w    = tid >> 5;
  const int lane = tid & 31;
  const int nblk = gridDim.x;
  const int totw = nblk * NWARPS;
  const int wg   = b * NWARPS + w;

  float* sA  = (float*)(sm + OFF_SA);
  float* sB  = (float*)(sm + OFF_SB);
  float* sLG = (float*)(sm + OFF_LG);
  int*   sAR = (int*)(sm + OFF_AROW);

  const uint32_t bar  = smu + OFF_MBAR + (uint32_t)w * NS * 8;
  const uint32_t ring = smu + OFF_RING + (uint32_t)w * NS * SLICE;
  const int ringoff   = OFF_RING + w * NS * SLICE;

  // per-warp slice accounting
  const int nr   = (wg < H4) ? ((H4 - 1 - wg) / totw + 1) : 0;
  const int nsl  = 4 * nr;        // slices per matrix per step
  const int nstep = 3 * nsl;      // slices per step
  const int ISS_MAX = TT * nstep;

  // ---------------- init ----------------
  for (int i = tid; i < HD; i += NTH) { sA[i] = 0.f; sB[i] = 0.f; }
  for (int i = tid; i < NWARPS * NS; i += NTH)
    mbar_init(smu + OFF_MBAR + (uint32_t)i * 8, 1u);
  if (tid == 0) *sAR = -1;
  __syncthreads();
  if (tid == 0)
    asm volatile("fence.proxy.async.shared::cta;" ::: "memory");
  // combined biases (grid-strided, disjoint)
  for (int i = b * NTH + tid; i < H4; i += nblk * NTH) {
    g_b1[i] = bih1[i] + bhh1[i];
    g_b2[i] = bih2[i] + bhh2[i];
  }
  // P1 = emb @ Wih1^T (warp per row)
  for (int r = wg; r < H4; r += totw) {
    float wreg[16];
    const float* wrow = Wih1 + (size_t)r * ED;
#pragma unroll
    for (int i = 0; i < 16; i++) wreg[i] = wrow[lane + i * 32];
    for (int m = 0; m < NEMB; m++) {
      const float* er = emb + m * ED;
      float p = 0.f;
#pragma unroll
      for (int i = 0; i < 16; i++) p += wreg[i] * er[lane + i * 32];
#pragma unroll
      for (int off = 16; off; off >>= 1) p += __shfl_xor_sync(0xffffffffu, p, off);
      if (lane == 0) g_P1[m * H4 + r] = p;
    }
  }
  grid_sync();

  // stream cursors + LSTM cell registers
  int iss = 0, con = 0;
  unsigned ph = 0;
  float acc = 0.f;
  float c1a = 0.f, c1b = 0.f, c2a = 0.f, c2b = 0.f;

  // prologue: fill ring
  for (int k = 0; k < NS && iss < ISS_MAX; k++) {
    if (lane == 0) issue_slice(iss, nsl, wg, totw, Whh1, Whh2, Wih2, ring, bar);
    iss++;
  }

  const int sizes[4] = {8, 6, 4, 5};
  const int offs[4]  = {0, 8, 14, 18};

  for (int t = 0; t < TT; t++) {
    const int arow = *sAR;
    float* dot2cur = g_dot2 + (size_t)(t & 1) * H4;

    // -------- stream segment A: Whh1.h1prev + Whh2.h2prev --------
    const int endA = t * nstep + 2 * nsl;
    while (con < endA) {
      consume_slice(con, nsl, wg, totw, sm, bar, ringoff, dot2cur, arow,
                    lane, &ph, &acc);
      con++;
      if (iss < ISS_MAX) {
        if (lane == 0) issue_slice(iss, nsl, wg, totw, Whh1, Whh2, Wih2, ring, bar);
        iss++;
      }
    }
    grid_sync();

    // -------- act1: h1 (redundant per block; cells in registers) --------
    {
      int u = tid;
      float di = __ldcg(&g_dot1[u]);
      float df = __ldcg(&g_dot1[u + 2048]);
      float dg = __ldcg(&g_dot1[u + 4096]);
      float dz = __ldcg(&g_dot1[u + 6144]);
      float c = sigm(df) * c1a + sigm(di) * tanhf(dg);
      c1a = c; sA[u] = sigm(dz) * tanhf(c);
      u = tid + NTH;
      di = __ldcg(&g_dot1[u]);
      df = __ldcg(&g_dot1[u + 2048]);
      dg = __ldcg(&g_dot1[u + 4096]);
      dz = __ldcg(&g_dot1[u + 6144]);
      c = sigm(df) * c1b + sigm(di) * tanhf(dg);
      c1b = c; sA[u] = sigm(dz) * tanhf(c);
    }
    __syncthreads();

    // -------- stream segment B: Wih2.h1new --------
    const int endB = (t + 1) * nstep;
    while (con < endB) {
      consume_slice(con, nsl, wg, totw, sm, bar, ringoff, dot2cur, arow,
                    lane, &ph, &acc);
      con++;
      if (iss < ISS_MAX) {
        if (lane == 0) issue_slice(iss, nsl, wg, totw, Whh1, Whh2, Wih2, ring, bar);
        iss++;
      }
    }
    grid_sync();

    // -------- act2: h2 --------
    {
      int u = tid;
      float di = __ldcg(&dot2cur[u])        + __ldcg(&g_dot3[u]);
      float df = __ldcg(&dot2cur[u + 2048]) + __ldcg(&g_dot3[u + 2048]);
      float dg = __ldcg(&dot2cur[u + 4096]) + __ldcg(&g_dot3[u + 4096]);
      float dz = __ldcg(&dot2cur[u + 6144]) + __ldcg(&g_dot3[u + 6144]);
      float c = sigm(df) * c2a + sigm(di) * tanhf(dg);
      c2a = c; sB[u] = sigm(dz) * tanhf(c);
      u = tid + NTH;
      di = __ldcg(&dot2cur[u])        + __ldcg(&g_dot3[u]);
      df = __ldcg(&dot2cur[u + 2048]) + __ldcg(&g_dot3[u + 2048]);
      dg = __ldcg(&dot2cur[u + 4096]) + __ldcg(&g_dot3[u + 4096]);
      dz = __ldcg(&dot2cur[u + 6144]) + __ldcg(&g_dot3[u + 6144]);
      c = sigm(df) * c2b + sigm(di) * tanhf(dg);
      c2b = c; sB[u] = sigm(dz) * tanhf(c);
    }
    __syncthreads();

    // -------- logits (8 parallel warps, redundant per block) --------
    if (w < 8) {
      const float4* wr = (const float4*)(Wout + ((size_t)t * MAXS + w) * HD);
      const float4* h4 = (const float4*)sB;
      float p = 0.f;
#pragma unroll 4
      for (int i = lane; i < HD / 4; i += 32) {
        float4 a = __ldg(&wr[i]); float4 h = h4[i];
        p += a.x * h.x + a.y * h.y + a.z * h.z + a.w * h.w;
      }
#pragma unroll
      for (int off = 16; off; off >>= 1) p += __shfl_xor_sync(0xffffffffu, p, off);
      if (lane == 0) sLG[w] = p + bout[t * MAXS + w];
    }
    __syncthreads();

    // -------- finalize sample (thread 0) --------
    if (tid == 0) {
      const int tp = t & 3;
      const int sz = sizes[tp];
      float l[8];
#pragma unroll
      for (int j = 0; j < 8; j++) l[j] = (j < sz) ? sLG[j] : -1e9f;

      unsigned k0, k1;
      threefry2x32(0u, 1u, 0u, (unsigned)t, &k0, &k1);
      unsigned bits[8];
#pragma unroll
      for (int i = 0; i < 8; i++) {
        unsigned a, bb;
        threefry2x32(k0, k1, 0u, (unsigned)i, &a, &bb);
        bits[i] = a ^ bb;
      }
      float gmb[8];
#pragma unroll
      for (int j = 0; j < 8; j++) {
        unsigned fb = (bits[j] >> 9) | 0x3f800000u;
        float uu = __uint_as_float(fb) - 1.0f;
        uu = fmaxf(TINYF, uu + TINYF);
        gmb[j] = -logf(-logf(uu));
      }
      int best = 0;
      float bv = l[0] + gmb[0];
#pragma unroll
      for (int j = 1; j < 8; j++) {
        float v = l[j] + gmb[j];
        if (v > bv) { bv = v; best = j; }
      }
      float m = l[0];
#pragma unroll
      for (int j = 1; j < 8; j++) m = fmaxf(m, l[j]);
      float s = 0.f;
#pragma unroll
      for (int j = 0; j < 8; j++) s += expf(l[j] - m);
      float prob = expf(l[best] - m) / s;

      *sAR = offs[tp] + best;
      if (b == 0) {
        out[t]      = (float)best;
        out[TT + t] = prob;
      }
    }
    __syncthreads();
  }
}

// ------------------------- launch -------------------------------------------
extern "C" void kernel_launch(void* const* d_in, const int* in_sizes, int n_in,
                              void* d_out, int out_size) {
  const float* emb  = (const float*)d_in[0];
  const float* Wih1 = (const float*)d_in[1];
  const float* Whh1 = (const float*)d_in[2];
  const float* bih1 = (const float*)d_in[3];
  const float* bhh1 = (const float*)d_in[4];
  const float* Wih2 = (const float*)d_in[5];
  const float* Whh2 = (const float*)d_in[6];
  const float* bih2 = (const float*)d_in[7];
  const float* bhh2 = (const float*)d_in[8];
  const float* Wout = (const float*)d_in[9];
  const float* bout = (const float*)d_in[10];
  (void)in_sizes; (void)n_in; (void)out_size;

  static int configured = 0;
  if (!configured) {
    cudaFuncSetAttribute(nas_lstm_kernel,
                         cudaFuncAttributeMaxDynamicSharedMemorySize, SMEM_TOTAL);
    configured = 1;
  }

  int dev = 0;
  cudaGetDevice(&dev);
  int sms = 0;
  cudaDeviceGetAttribute(&sms, cudaDevAttrMultiProcessorCount, dev);
  int occ = 0;
  cudaOccupancyMaxActiveBlocksPerMultiprocessor(&occ, nas_lstm_kernel, NTH,
                                                SMEM_TOTAL);
  if (occ < 1) occ = 1;
  int nblk = sms * occ;
  if (nblk > 128) nblk = 128;   // 128*32 warps divide 8192 rows exactly
  if (nblk < 1) nblk = 1;

  nas_lstm_kernel<<<nblk, NTH, SMEM_TOTAL>>>(emb, Wih1, Whh1, bih1, bhh1,
                                             Wih2, Whh2, bih2, bhh2,
                                             Wout, bout, (float*)d_out);
}

// round 5
// speedup vs baseline: 1.2005x; 1.0155x over previous
#include <cuda_runtime.h>
#include <math.h>
#include <stdint.h>

// ---------------------------------------------------------------------------
// NAS-controller LSTM, persistent kernel v5.
//  - per-WARP TMA rings (3 x 2KB, private mbarriers), issue-ahead across
//    phases and grid barriers
//  - L2 residency split: Whh1 + Wih2[0:4096) tagged evict_last (96MB resident
//    across steps), Whh2 + Wih2[4096:) evict_first (streamed)
//  - counter-based cursors (no div/mod in hot loop), tight-poll grid barrier
//  - bias + P1(action) folded into streamed row stores; cells in registers
//  - threefry2x32 partitionable path (verified bit-exact)
// ---------------------------------------------------------------------------

#define HD    2048
#define H4    8192
#define ED    512
#define TT    48
#define MAXS  8
#define NEMB  23
#define NTH   1024
#define NWARPS 32
#define TINYF 1.17549435e-38f

#define NS    3                   // ring slots per warp
#define SLICE 2048                // bytes per slice (512 floats)
#define KCH   512                 // floats per K-chunk

// smem layout (bytes)
#define OFF_SA    0
#define OFF_SB    8192
#define OFF_LG    16384
#define OFF_AROW  16416
#define OFF_MBAR  16432                      // 32*3*8 = 768
#define OFF_RING  17408                      // 32*3*2048 = 196608
#define SMEM_TOTAL (OFF_RING + NWARPS * NS * SLICE)   // 214016

// ------------------------- device scratch ----------------------------------
__device__ float    g_P1[NEMB * H4];
__device__ float    g_dot1[H4];        // Whh1.h1 (+bias+P1)
__device__ float    g_dot2[2 * H4];    // Whh2.h2, step-parity double buffered
__device__ float    g_dot3[H4];        // Wih2.h1new (+bias)
__device__ float    g_b1[H4];          // bih1+bhh1
__device__ float    g_b2[H4];          // bih2+bhh2
__device__ unsigned g_count = 0;
__device__ unsigned g_gen   = 0;

// ------------------------- grid barrier (tight poll) ------------------------
__device__ __forceinline__ void grid_sync() {
  __threadfence();
  __syncthreads();
  if (threadIdx.x == 0) {
    volatile unsigned* vg = (volatile unsigned*)&g_gen;
    unsigned gen = *vg;
    __threadfence();
    if (atomicAdd(&g_count, 1u) == (unsigned)(gridDim.x - 1)) {
      g_count = 0u;
      __threadfence();
      atomicAdd(&g_gen, 1u);
    } else {
      while (*vg == gen) { }     // tight poll: L2 hit ~250cyc wake
    }
  }
  __syncthreads();
}

// ------------------------- mbarrier / bulk copy -----------------------------
__device__ __forceinline__ uint32_t smem_u32(const void* p) {
  uint32_t a;
  asm("{ .reg .u64 t; cvta.to.shared.u64 t, %1; cvt.u32.u64 %0, t; }"
      : "=r"(a) : "l"(p));
  return a;
}
__device__ __forceinline__ void mbar_init(uint32_t a, uint32_t cnt) {
  asm volatile("mbarrier.init.shared.b64 [%0], %1;" :: "r"(a), "r"(cnt) : "memory");
}
__device__ __forceinline__ void mbar_expect(uint32_t a, uint32_t tx) {
  asm volatile("mbarrier.arrive.expect_tx.shared.b64 _, [%0], %1;"
               :: "r"(a), "r"(tx) : "memory");
}
__device__ __forceinline__ void mbar_wait(uint32_t a, unsigned ph) {
  asm volatile(
      "{\n\t.reg .pred P;\n"
      "W%=:\n\t"
      "mbarrier.try_wait.parity.shared.b64 P, [%0], %1;\n\t"
      "@P bra D%=;\n\t"
      "bra W%=;\n"
      "D%=:\n\t}"
      :: "r"(a), "r"(ph) : "memory");
}
__device__ __forceinline__ void bulk_g2s_hint(uint32_t dst, const float* src,
                                              uint32_t bytes, uint32_t bar,
                                              uint64_t pol) {
  asm volatile(
      "cp.async.bulk.shared::cluster.global.mbarrier::complete_tx::bytes"
      ".L2::cache_hint [%0], [%1], %2, [%3], %4;"
      :: "r"(dst), "l"(src), "r"(bytes), "r"(bar), "l"(pol) : "memory");
}

// ------------------------- threefry2x32 (verified exact) --------------------
__device__ __forceinline__ unsigned rotl32(unsigned x, int r) {
  return (x << r) | (x >> (32 - r));
}
__device__ __forceinline__ void threefry2x32(unsigned k0, unsigned k1,
                                             unsigned x0, unsigned x1,
                                             unsigned* o0, unsigned* o1) {
  unsigned ks0 = k0, ks1 = k1, ks2 = k0 ^ k1 ^ 0x1BD11BDAu;
  x0 += ks0; x1 += ks1;
  x0 += x1; x1 = rotl32(x1, 13); x1 ^= x0;
  x0 += x1; x1 = rotl32(x1, 15); x1 ^= x0;
  x0 += x1; x1 = rotl32(x1, 26); x1 ^= x0;
  x0 += x1; x1 = rotl32(x1, 6);  x1 ^= x0;
  x0 += ks1; x1 += ks2 + 1u;
  x0 += x1; x1 = rotl32(x1, 17); x1 ^= x0;
  x0 += x1; x1 = rotl32(x1, 29); x1 ^= x0;
  x0 += x1; x1 = rotl32(x1, 16); x1 ^= x0;
  x0 += x1; x1 = rotl32(x1, 24); x1 ^= x0;
  x0 += ks2; x1 += ks0 + 2u;
  x0 += x1; x1 = rotl32(x1, 13); x1 ^= x0;
  x0 += x1; x1 = rotl32(x1, 15); x1 ^= x0;
  x0 += x1; x1 = rotl32(x1, 26); x1 ^= x0;
  x0 += x1; x1 = rotl32(x1, 6);  x1 ^= x0;
  x0 += ks0; x1 += ks1 + 3u;
  x0 += x1; x1 = rotl32(x1, 17); x1 ^= x0;
  x0 += x1; x1 = rotl32(x1, 29); x1 ^= x0;
  x0 += x1; x1 = rotl32(x1, 16); x1 ^= x0;
  x0 += x1; x1 = rotl32(x1, 24); x1 ^= x0;
  x0 += ks1; x1 += ks2 + 4u;
  x0 += x1; x1 = rotl32(x1, 13); x1 ^= x0;
  x0 += x1; x1 = rotl32(x1, 15); x1 ^= x0;
  x0 += x1; x1 = rotl32(x1, 26); x1 ^= x0;
  x0 += x1; x1 = rotl32(x1, 6);  x1 ^= x0;
  x0 += ks2; x1 += ks0 + 5u;
  *o0 = x0; *o1 = x1;
}

__device__ __forceinline__ float sigm(float x) { return 1.0f / (1.0f + expf(-x)); }

// ------------------------- main persistent kernel ---------------------------
__global__ void __launch_bounds__(NTH, 1)
nas_lstm_kernel(const float* __restrict__ emb,
                const float* __restrict__ Wih1, const float* __restrict__ Whh1,
                const float* __restrict__ bih1, const float* __restrict__ bhh1,
                const float* __restrict__ Wih2, const float* __restrict__ Whh2,
                const float* __restrict__ bih2, const float* __restrict__ bhh2,
                const float* __restrict__ Wout, const float* __restrict__ bout,
                float* __restrict__ out) {
  extern __shared__ __align__(16) char sm[];
  const uint32_t smu = smem_u32(sm);

  const int tid  = threadIdx.x;
  const int b    = blockIdx.x;
  const int w    = tid >> 5;
  const int lane = tid & 31;
  const int nblk = gridDim.x;
  const int totw = nblk * NWARPS;
  const int wg   = b * NWARPS + w;

  float* sA  = (float*)(sm + OFF_SA);
  float* sB  = (float*)(sm + OFF_SB);
  float* sLG = (float*)(sm + OFF_LG);
  int*   sAR = (int*)(sm + OFF_AROW);

  const uint32_t bar  = smu + OFF_MBAR + (uint32_t)w * NS * 8;
  const uint32_t ring = smu + OFF_RING + (uint32_t)w * NS * SLICE;
  const int ringoff   = OFF_RING + w * NS * SLICE;

  // L2 policies: evict_last = resident, evict_first = streaming
  uint64_t polL, polF;
  asm("createpolicy.fractional.L2::evict_last.b64 %0, 1.0;" : "=l"(polL));
  asm("createpolicy.fractional.L2::evict_first.b64 %0, 1.0;" : "=l"(polF));

  // per-warp slice accounting
  const int nr  = (wg < H4) ? ((H4 - 1 - wg) / totw + 1) : 0;
  const int nsl = 4 * nr;                 // slices per matrix per step
  const long ISS_MAX = (long)TT * 3 * nsl;

  // ---------------- init ----------------
  for (int i = tid; i < HD; i += NTH) { sA[i] = 0.f; sB[i] = 0.f; }
  for (int i = tid; i < NWARPS * NS; i += NTH)
    mbar_init(smu + OFF_MBAR + (uint32_t)i * 8, 1u);
  if (tid == 0) *sAR = -1;
  __syncthreads();
  if (tid == 0)
    asm volatile("fence.proxy.async.shared::cta;" ::: "memory");
  // combined biases (grid-strided, disjoint)
  for (int i = b * NTH + tid; i < H4; i += nblk * NTH) {
    g_b1[i] = bih1[i] + bhh1[i];
    g_b2[i] = bih2[i] + bhh2[i];
  }
  // P1 = emb @ Wih1^T (warp per row)
  for (int r = wg; r < H4; r += totw) {
    float wreg[16];
    const float* wrow = Wih1 + (size_t)r * ED;
#pragma unroll
    for (int i = 0; i < 16; i++) wreg[i] = wrow[lane + i * 32];
    for (int m = 0; m < NEMB; m++) {
      const float* er = emb + m * ED;
      float p = 0.f;
#pragma unroll
      for (int i = 0; i < 16; i++) p += wreg[i] * er[lane + i * 32];
#pragma unroll
      for (int off = 16; off; off >>= 1) p += __shfl_xor_sync(0xffffffffu, p, off);
      if (lane == 0) g_P1[m * H4 + r] = p;
    }
  }
  grid_sync();

  // ---- stream cursors (counter-based, no div/mod) ----
  int i_seg = 0, i_s = 0, i_slot = 0;   // issue: segment, slice-in-seg, slot
  int c_seg = 0, c_s = 0, c_slot = 0;   // consume
  long issued = 0;
  unsigned ph = 0;
  float acc = 0.f;
  float c1a = 0.f, c1b = 0.f, c2a = 0.f, c2b = 0.f;

#define ISSUE_ONE()                                                            \
  do {                                                                         \
    if (lane == 0) {                                                           \
      const int row_ = wg + (i_s >> 2) * totw;                                 \
      const int kc_ = i_s & 3;                                                 \
      const float* W_; uint64_t pol_;                                          \
      if (i_seg == 0)      { W_ = Whh1; pol_ = polL; }                         \
      else if (i_seg == 1) { W_ = Whh2; pol_ = polF; }                         \
      else                 { W_ = Wih2; pol_ = (row_ < 4096) ? polL : polF; }  \
      const uint32_t ba_ = bar + i_slot * 8;                                   \
      mbar_expect(ba_, SLICE);                                                 \
      bulk_g2s_hint(ring + i_slot * SLICE,                                     \
                    W_ + (size_t)row_ * HD + kc_ * KCH, SLICE, ba_, pol_);     \
    }                                                                          \
    if (++i_slot == NS) i_slot = 0;                                            \
    if (++i_s == nsl) { i_s = 0; if (++i_seg == 3) i_seg = 0; }                \
    issued++;                                                                  \
  } while (0)

#define CONSUME_ONE(dot2cur, arow)                                             \
  do {                                                                         \
    mbar_wait(bar + c_slot * 8, (ph >> c_slot) & 1u);                          \
    ph ^= (1u << c_slot);                                                      \
    const int row_ = wg + (c_s >> 2) * totw;                                   \
    const int kc_ = c_s & 3;                                                   \
    const float* hv_; float* dst_;                                             \
    if (c_seg == 0)      { hv_ = sA; dst_ = g_dot1; }                          \
    else if (c_seg == 1) { hv_ = sB; dst_ = (dot2cur); }                       \
    else                 { hv_ = sA; dst_ = g_dot3; }                          \
    const float4* wp_ = (const float4*)(sm + ringoff + c_slot * SLICE);        \
    const float4* hp_ = (const float4*)hv_ + kc_ * 128;                        \
    _Pragma("unroll")                                                          \
    for (int i_ = 0; i_ < 4; i_++) {                                           \
      const int j_ = lane + i_ * 32;                                           \
      float4 x_ = wp_[j_], h_ = hp_[j_];                                       \
      acc += x_.x * h_.x + x_.y * h_.y + x_.z * h_.z + x_.w * h_.w;            \
    }                                                                          \
    if (kc_ == 3) {                                                            \
      _Pragma("unroll")                                                        \
      for (int o_ = 16; o_; o_ >>= 1)                                          \
        acc += __shfl_xor_sync(0xffffffffu, acc, o_);                          \
      if (lane == 0) {                                                         \
        float ex_ = 0.f;                                                       \
        if (c_seg == 0) {                                                      \
          ex_ = __ldcg(&g_b1[row_]);                                           \
          if ((arow) >= 0)                                                     \
            ex_ += __ldcg(&g_P1[(size_t)(arow) * H4 + row_]);                  \
        } else if (c_seg == 2) {                                               \
          ex_ = __ldcg(&g_b2[row_]);                                           \
        }                                                                      \
        __stcg(&dst_[row_], acc + ex_);                                        \
      }                                                                        \
      acc = 0.f;                                                               \
    }                                                                          \
    if (++c_slot == NS) c_slot = 0;                                            \
    if (++c_s == nsl) { c_s = 0; if (++c_seg == 3) c_seg = 0; }                \
  } while (0)

  // prologue: fill ring
  for (int k = 0; k < NS; k++)
    if (issued < ISS_MAX) ISSUE_ONE();

  const int sizes[4] = {8, 6, 4, 5};
  const int offs[4]  = {0, 8, 14, 18};

  for (int t = 0; t < TT; t++) {
    const int arow = *sAR;
    float* dot2cur = g_dot2 + (size_t)(t & 1) * H4;

    // -------- segment A: Whh1.h1prev + Whh2.h2prev --------
    for (int k = 0; k < 2 * nsl; k++) {
      CONSUME_ONE(dot2cur, arow);
      if (issued < ISS_MAX) ISSUE_ONE();
    }
    grid_sync();

    // -------- act1: h1 (redundant per block; cells in registers) --------
    {
      int u = tid;
      float di = __ldcg(&g_dot1[u]);
      float df = __ldcg(&g_dot1[u + 2048]);
      float dg = __ldcg(&g_dot1[u + 4096]);
      float dz = __ldcg(&g_dot1[u + 6144]);
      float c = sigm(df) * c1a + sigm(di) * tanhf(dg);
      c1a = c; sA[u] = sigm(dz) * tanhf(c);
      u = tid + NTH;
      di = __ldcg(&g_dot1[u]);
      df = __ldcg(&g_dot1[u + 2048]);
      dg = __ldcg(&g_dot1[u + 4096]);
      dz = __ldcg(&g_dot1[u + 6144]);
      c = sigm(df) * c1b + sigm(di) * tanhf(dg);
      c1b = c; sA[u] = sigm(dz) * tanhf(c);
    }
    __syncthreads();

    // -------- segment B: Wih2.h1new --------
    for (int k = 0; k < nsl; k++) {
      CONSUME_ONE(dot2cur, arow);
      if (issued < ISS_MAX) ISSUE_ONE();
    }
    grid_sync();

    // -------- act2: h2 --------
    {
      int u = tid;
      float di = __ldcg(&dot2cur[u])        + __ldcg(&g_dot3[u]);
      float df = __ldcg(&dot2cur[u + 2048]) + __ldcg(&g_dot3[u + 2048]);
      float dg = __ldcg(&dot2cur[u + 4096]) + __ldcg(&g_dot3[u + 4096]);
      float dz = __ldcg(&dot2cur[u + 6144]) + __ldcg(&g_dot3[u + 6144]);
      float c = sigm(df) * c2a + sigm(di) * tanhf(dg);
      c2a = c; sB[u] = sigm(dz) * tanhf(c);
      u = tid + NTH;
      di = __ldcg(&dot2cur[u])        + __ldcg(&g_dot3[u]);
      df = __ldcg(&dot2cur[u + 2048]) + __ldcg(&g_dot3[u + 2048]);
      dg = __ldcg(&dot2cur[u + 4096]) + __ldcg(&g_dot3[u + 4096]);
      dz = __ldcg(&dot2cur[u + 6144]) + __ldcg(&g_dot3[u + 6144]);
      c = sigm(df) * c2b + sigm(di) * tanhf(dg);
      c2b = c; sB[u] = sigm(dz) * tanhf(c);
    }
    __syncthreads();

    // -------- logits (8 parallel warps, redundant per block) --------
    if (w < 8) {
      const float4* wr = (const float4*)(Wout + ((size_t)t * MAXS + w) * HD);
      const float4* h4 = (const float4*)sB;
      float p = 0.f;
#pragma unroll 4
      for (int i = lane; i < HD / 4; i += 32) {
        float4 a = __ldg(&wr[i]); float4 h = h4[i];
        p += a.x * h.x + a.y * h.y + a.z * h.z + a.w * h.w;
      }
#pragma unroll
      for (int off = 16; off; off >>= 1) p += __shfl_xor_sync(0xffffffffu, p, off);
      if (lane == 0) sLG[w] = p + bout[t * MAXS + w];
    }
    __syncthreads();

    // -------- finalize sample (thread 0) --------
    if (tid == 0) {
      const int tp = t & 3;
      const int sz = sizes[tp];
      float l[8];
#pragma unroll
      for (int j = 0; j < 8; j++) l[j] = (j < sz) ? sLG[j] : -1e9f;

      unsigned k0, k1;
      threefry2x32(0u, 1u, 0u, (unsigned)t, &k0, &k1);
      unsigned bits[8];
#pragma unroll
      for (int i = 0; i < 8; i++) {
        unsigned a, bb;
        threefry2x32(k0, k1, 0u, (unsigned)i, &a, &bb);
        bits[i] = a ^ bb;
      }
      float gmb[8];
#pragma unroll
      for (int j = 0; j < 8; j++) {
        unsigned fb = (bits[j] >> 9) | 0x3f800000u;
        float uu = __uint_as_float(fb) - 1.0f;
        uu = fmaxf(TINYF, uu + TINYF);
        gmb[j] = -logf(-logf(uu));
      }
      int best = 0;
      float bv = l[0] + gmb[0];
#pragma unroll
      for (int j = 1; j < 8; j++) {
        float v = l[j] + gmb[j];
        if (v > bv) { bv = v; best = j; }
      }
      float m = l[0];
#pragma unroll
      for (int j = 1; j < 8; j++) m = fmaxf(m, l[j]);
      float s = 0.f;
#pragma unroll
      for (int j = 0; j < 8; j++) s += expf(l[j] - m);
      float prob = expf(l[best] - m) / s;

      *sAR = offs[tp] + best;
      if (b == 0) {
        out[t]      = (float)best;
        out[TT + t] = prob;
      }
    }
    __syncthreads();
  }
}

// ------------------------- launch -------------------------------------------
extern "C" void kernel_launch(void* const* d_in, const int* in_sizes, int n_in,
                              void* d_out, int out_size) {
  const float* emb  = (const float*)d_in[0];
  const float* Wih1 = (const float*)d_in[1];
  const float* Whh1 = (const float*)d_in[2];
  const float* bih1 = (const float*)d_in[3];
  const float* bhh1 = (const float*)d_in[4];
  const float* Wih2 = (const float*)d_in[5];
  const float* Whh2 = (const float*)d_in[6];
  const float* bih2 = (const float*)d_in[7];
  const float* bhh2 = (const float*)d_in[8];
  const float* Wout = (const float*)d_in[9];
  const float* bout = (const float*)d_in[10];
  (void)in_sizes; (void)n_in; (void)out_size;

  static int configured = 0;
  if (!configured) {
    cudaFuncSetAttribute(nas_lstm_kernel,
                         cudaFuncAttributeMaxDynamicSharedMemorySize, SMEM_TOTAL);
    configured = 1;
  }

  int dev = 0;
  cudaGetDevice(&dev);
  int sms = 0;
  cudaDeviceGetAttribute(&sms, cudaDevAttrMultiProcessorCount, dev);
  int occ = 0;
  cudaOccupancyMaxActiveBlocksPerMultiprocessor(&occ, nas_lstm_kernel, NTH,
                                                SMEM_TOTAL);
  if (occ < 1) occ = 1;
  int nblk = sms * occ;
  if (nblk > 128) nblk = 128;   // 128*32 warps divide 8192 rows exactly
  if (nblk < 1) nblk = 1;

  nas_lstm_kernel<<<nblk, NTH, SMEM_TOTAL>>>(emb, Wih1, Whh1, bih1, bhh1,
                                             Wih2, Whh2, bih2, bhh2,
                                             Wout, bout, (float*)d_out);
}

// round 6
// speedup vs baseline: 1.7470x; 1.4552x over previous
#include <cuda_runtime.h>
#include <cuda_fp16.h>
#include <math.h>
#include <stdint.h>

// ---------------------------------------------------------------------------
// NAS-controller LSTM, persistent kernel v6.
//  - weights converted fp32 -> fp16 ONCE per launch into __device__ scratch
//    (96MB; fits L2 entirely -> evict_last TMA hints keep them resident)
//  - per-WARP TMA rings (3 x 2KB fp16 slices), issue-ahead across phases
//  - h staged in fp16 smem (halves LDS); fp32 accumulate for accuracy
//  - bias + P1(action) applied in act1/act2 (streaming independent of action)
//  - threefry2x32 partitionable path (verified bit-exact)
// ---------------------------------------------------------------------------

#define HD    2048
#define H4    8192
#define ED    512
#define TT    48
#define MAXS  8
#define NEMB  23
#define NTH   1024
#define NWARPS 32
#define TINYF 1.17549435e-38f

#define NS       3                 // ring slots per warp
#define SLICE_B  2048              // bytes per slice = 1024 halves
#define MAT_ELEM (H4 * HD)         // 16777216 halves per matrix

// smem layout (bytes)
#define OFF_SAH   0                // h1 staged fp16 (2048 * 2 = 4096)
#define OFF_SBH   4096             // h2 staged fp16
#define OFF_LG    8192             // 8 logits
#define OFF_AROW  8224
#define OFF_MBAR  8240             // 32*3*8 = 768
#define OFF_RING  9216             // 32*3*2048 = 196608 (128B aligned)
#define SMEM_TOTAL (OFF_RING + NWARPS * NS * SLICE_B)   // 205824

// ------------------------- device scratch ----------------------------------
__device__ __half   g_Wh[3 * MAT_ELEM];   // [Whh1 | Whh2 | Wih2] fp16 (96MB)
__device__ float    g_P1[NEMB * H4];
__device__ float    g_dot1[H4];           // Whh1.h1
__device__ float    g_dot2[2 * H4];       // Whh2.h2 (step-parity buffered)
__device__ float    g_dot3[H4];           // Wih2.h1new
__device__ float    g_b1[H4];             // bih1+bhh1
__device__ float    g_b2[H4];             // bih2+bhh2
__device__ unsigned g_count = 0;
__device__ unsigned g_gen   = 0;

// ------------------------- grid barrier (tight poll) ------------------------
__device__ __forceinline__ void grid_sync() {
  __threadfence();
  __syncthreads();
  if (threadIdx.x == 0) {
    volatile unsigned* vg = (volatile unsigned*)&g_gen;
    unsigned gen = *vg;
    __threadfence();
    if (atomicAdd(&g_count, 1u) == (unsigned)(gridDim.x - 1)) {
      g_count = 0u;
      __threadfence();
      atomicAdd(&g_gen, 1u);
    } else {
      while (*vg == gen) { }
    }
  }
  __syncthreads();
}

// ------------------------- mbarrier / bulk copy -----------------------------
__device__ __forceinline__ uint32_t smem_u32(const void* p) {
  uint32_t a;
  asm("{ .reg .u64 t; cvta.to.shared.u64 t, %1; cvt.u32.u64 %0, t; }"
      : "=r"(a) : "l"(p));
  return a;
}
__device__ __forceinline__ void mbar_init(uint32_t a, uint32_t cnt) {
  asm volatile("mbarrier.init.shared.b64 [%0], %1;" :: "r"(a), "r"(cnt) : "memory");
}
__device__ __forceinline__ void mbar_expect(uint32_t a, uint32_t tx) {
  asm volatile("mbarrier.arrive.expect_tx.shared.b64 _, [%0], %1;"
               :: "r"(a), "r"(tx) : "memory");
}
__device__ __forceinline__ void mbar_wait(uint32_t a, unsigned ph) {
  asm volatile(
      "{\n\t.reg .pred P;\n"
      "W%=:\n\t"
      "mbarrier.try_wait.parity.shared.b64 P, [%0], %1;\n\t"
      "@P bra D%=;\n\t"
      "bra W%=;\n"
      "D%=:\n\t}"
      :: "r"(a), "r"(ph) : "memory");
}
__device__ __forceinline__ void bulk_g2s_hint(uint32_t dst, const void* src,
                                              uint32_t bytes, uint32_t bar,
                                              uint64_t pol) {
  asm volatile(
      "cp.async.bulk.shared::cluster.global.mbarrier::complete_tx::bytes"
      ".L2::cache_hint [%0], [%1], %2, [%3], %4;"
      :: "r"(dst), "l"(src), "r"(bytes), "r"(bar), "l"(pol) : "memory");
}

// ------------------------- threefry2x32 (verified exact) --------------------
__device__ __forceinline__ unsigned rotl32(unsigned x, int r) {
  return (x << r) | (x >> (32 - r));
}
__device__ __forceinline__ void threefry2x32(unsigned k0, unsigned k1,
                                             unsigned x0, unsigned x1,
                                             unsigned* o0, unsigned* o1) {
  unsigned ks0 = k0, ks1 = k1, ks2 = k0 ^ k1 ^ 0x1BD11BDAu;
  x0 += ks0; x1 += ks1;
  x0 += x1; x1 = rotl32(x1, 13); x1 ^= x0;
  x0 += x1; x1 = rotl32(x1, 15); x1 ^= x0;
  x0 += x1; x1 = rotl32(x1, 26); x1 ^= x0;
  x0 += x1; x1 = rotl32(x1, 6);  x1 ^= x0;
  x0 += ks1; x1 += ks2 + 1u;
  x0 += x1; x1 = rotl32(x1, 17); x1 ^= x0;
  x0 += x1; x1 = rotl32(x1, 29); x1 ^= x0;
  x0 += x1; x1 = rotl32(x1, 16); x1 ^= x0;
  x0 += x1; x1 = rotl32(x1, 24); x1 ^= x0;
  x0 += ks2; x1 += ks0 + 2u;
  x0 += x1; x1 = rotl32(x1, 13); x1 ^= x0;
  x0 += x1; x1 = rotl32(x1, 15); x1 ^= x0;
  x0 += x1; x1 = rotl32(x1, 26); x1 ^= x0;
  x0 += x1; x1 = rotl32(x1, 6);  x1 ^= x0;
  x0 += ks0; x1 += ks1 + 3u;
  x0 += x1; x1 = rotl32(x1, 17); x1 ^= x0;
  x0 += x1; x1 = rotl32(x1, 29); x1 ^= x0;
  x0 += x1; x1 = rotl32(x1, 16); x1 ^= x0;
  x0 += x1; x1 = rotl32(x1, 24); x1 ^= x0;
  x0 += ks1; x1 += ks2 + 4u;
  x0 += x1; x1 = rotl32(x1, 13); x1 ^= x0;
  x0 += x1; x1 = rotl32(x1, 15); x1 ^= x0;
  x0 += x1; x1 = rotl32(x1, 26); x1 ^= x0;
  x0 += x1; x1 = rotl32(x1, 6);  x1 ^= x0;
  x0 += ks2; x1 += ks0 + 5u;
  *o0 = x0; *o1 = x1;
}

__device__ __forceinline__ float sigm(float x) { return 1.0f / (1.0f + expf(-x)); }

__device__ __forceinline__ float dotH2(unsigned wu, unsigned hu) {
  __half2 wh = *(__half2*)&wu;
  __half2 hh = *(__half2*)&hu;
  float2 wf = __half22float2(wh);
  float2 hf = __half22float2(hh);
  return wf.x * hf.x + wf.y * hf.y;
}

// ------------------------- main persistent kernel ---------------------------
__global__ void __launch_bounds__(NTH, 1)
nas_lstm_kernel(const float* __restrict__ emb,
                const float* __restrict__ Wih1, const float* __restrict__ Whh1,
                const float* __restrict__ bih1, const float* __restrict__ bhh1,
                const float* __restrict__ Wih2, const float* __restrict__ Whh2,
                const float* __restrict__ bih2, const float* __restrict__ bhh2,
                const float* __restrict__ Wout, const float* __restrict__ bout,
                float* __restrict__ out) {
  extern __shared__ __align__(16) char sm[];
  const uint32_t smu = smem_u32(sm);

  const int tid  = threadIdx.x;
  const int b    = blockIdx.x;
  const int w    = tid >> 5;
  const int lane = tid & 31;
  const int nblk = gridDim.x;
  const int totw = nblk * NWARPS;
  const int wg   = b * NWARPS + w;

  __half* sAh = (__half*)(sm + OFF_SAH);
  __half* sBh = (__half*)(sm + OFF_SBH);
  float*  sLG = (float*)(sm + OFF_LG);
  int*    sAR = (int*)(sm + OFF_AROW);

  const uint32_t bar  = smu + OFF_MBAR + (uint32_t)w * NS * 8;
  const uint32_t ring = smu + OFF_RING + (uint32_t)w * NS * SLICE_B;
  const int ringoff   = OFF_RING + w * NS * SLICE_B;

  uint64_t polL;
  asm("createpolicy.fractional.L2::evict_last.b64 %0, 1.0;" : "=l"(polL));

  // per-warp slice accounting: 2 slices per row (1024 halves each)
  const int nr  = (wg < H4) ? ((H4 - 1 - wg) / totw + 1) : 0;
  const int nsl = 2 * nr;                 // slices per matrix per step
  const long ISS_MAX = (long)TT * 3 * nsl;

  // ---------------- init ----------------
  for (int i = tid; i < HD; i += NTH) {
    sAh[i] = __float2half_rn(0.f);
    sBh[i] = __float2half_rn(0.f);
  }
  for (int i = tid; i < NWARPS * NS; i += NTH)
    mbar_init(smu + OFF_MBAR + (uint32_t)i * 8, 1u);
  if (tid == 0) *sAR = -1;
  __syncthreads();
  if (tid == 0)
    asm volatile("fence.proxy.async.shared::cta;" ::: "memory");

  // combined biases (grid-strided, disjoint)
  for (int i = b * NTH + tid; i < H4; i += nblk * NTH) {
    g_b1[i] = bih1[i] + bhh1[i];
    g_b2[i] = bih2[i] + bhh2[i];
  }
  // fp32 -> fp16 conversion of the three streamed matrices
  {
    const int M4 = MAT_ELEM / 4;                  // float4 groups per matrix
    uint2* dst = (uint2*)g_Wh;
    for (long i = (long)b * NTH + tid; i < 3L * M4; i += (long)nblk * NTH) {
      float4 v;
      if (i < M4)            v = __ldg(&((const float4*)Whh1)[i]);
      else if (i < 2L * M4)  v = __ldg(&((const float4*)Whh2)[i - M4]);
      else                   v = __ldg(&((const float4*)Wih2)[i - 2L * M4]);
      __half2 lo = __floats2half2_rn(v.x, v.y);
      __half2 hi = __floats2half2_rn(v.z, v.w);
      uint2 u;
      u.x = *(unsigned*)&lo;
      u.y = *(unsigned*)&hi;
      dst[i] = u;
    }
  }
  // P1 = emb @ Wih1^T (warp per row, fp32)
  for (int r = wg; r < H4; r += totw) {
    float wreg[16];
    const float* wrow = Wih1 + (size_t)r * ED;
#pragma unroll
    for (int i = 0; i < 16; i++) wreg[i] = wrow[lane + i * 32];
    for (int m = 0; m < NEMB; m++) {
      const float* er = emb + m * ED;
      float p = 0.f;
#pragma unroll
      for (int i = 0; i < 16; i++) p += wreg[i] * er[lane + i * 32];
#pragma unroll
      for (int off = 16; off; off >>= 1) p += __shfl_xor_sync(0xffffffffu, p, off);
      if (lane == 0) g_P1[m * H4 + r] = p;
    }
  }
  grid_sync();

  // ---- stream cursors ----
  int i_seg = 0, i_s = 0, i_slot = 0;
  int c_seg = 0, c_s = 0, c_slot = 0;
  long issued = 0;
  unsigned ph = 0;
  float acc = 0.f;
  float c1a = 0.f, c1b = 0.f, c2a = 0.f, c2b = 0.f;

#define ISSUE_ONE()                                                            \
  do {                                                                         \
    if (lane == 0) {                                                           \
      const int row_ = wg + (i_s >> 1) * totw;                                 \
      const int kc_ = i_s & 1;                                                 \
      const __half* src_ = g_Wh + ((size_t)i_seg * MAT_ELEM) +                 \
                           ((size_t)row_ << 11) + (kc_ << 10);                 \
      const uint32_t ba_ = bar + i_slot * 8;                                   \
      mbar_expect(ba_, SLICE_B);                                               \
      bulk_g2s_hint(ring + i_slot * SLICE_B, src_, SLICE_B, ba_, polL);        \
    }                                                                          \
    if (++i_slot == NS) i_slot = 0;                                            \
    if (++i_s == nsl) { i_s = 0; if (++i_seg == 3) i_seg = 0; }                \
    issued++;                                                                  \
  } while (0)

#define CONSUME_ONE(dot2cur)                                                   \
  do {                                                                         \
    mbar_wait(bar + c_slot * 8, (ph >> c_slot) & 1u);                          \
    ph ^= (1u << c_slot);                                                      \
    const int row_ = wg + (c_s >> 1) * totw;                                   \
    const int kc_ = c_s & 1;                                                   \
    float* dst_;                                                               \
    const uint4* hq_;                                                          \
    if (c_seg == 0)      { hq_ = (const uint4*)(sm + OFF_SAH); dst_ = g_dot1; }\
    else if (c_seg == 1) { hq_ = (const uint4*)(sm + OFF_SBH); dst_ = (dot2cur); }\
    else                 { hq_ = (const uint4*)(sm + OFF_SAH); dst_ = g_dot3; }\
    hq_ += (kc_ << 7);                                                         \
    const uint4* wp_ = (const uint4*)(sm + ringoff + c_slot * SLICE_B);        \
    _Pragma("unroll")                                                          \
    for (int i_ = 0; i_ < 4; i_++) {                                           \
      const int j_ = lane + i_ * 32;                                           \
      uint4 wv_ = wp_[j_];                                                     \
      uint4 hv_ = hq_[j_];                                                     \
      acc += dotH2(wv_.x, hv_.x) + dotH2(wv_.y, hv_.y)                         \
           + dotH2(wv_.z, hv_.z) + dotH2(wv_.w, hv_.w);                        \
    }                                                                          \
    if (kc_ == 1) {                                                            \
      _Pragma("unroll")                                                        \
      for (int o_ = 16; o_; o_ >>= 1)                                          \
        acc += __shfl_xor_sync(0xffffffffu, acc, o_);                          \
      if (lane == 0) __stcg(&dst_[row_], acc);                                 \
      acc = 0.f;                                                               \
    }                                                                          \
    if (++c_slot == NS) c_slot = 0;                                            \
    if (++c_s == nsl) { c_s = 0; if (++c_seg == 3) c_seg = 0; }                \
  } while (0)

  // prologue: fill ring
  for (int k = 0; k < NS; k++)
    if (issued < ISS_MAX) ISSUE_ONE();

  const int sizes[4] = {8, 6, 4, 5};
  const int offs[4]  = {0, 8, 14, 18};

  for (int t = 0; t < TT; t++) {
    const int arow = *sAR;
    float* dot2cur = g_dot2 + (size_t)(t & 1) * H4;

    // -------- segment A: Whh1.h1prev + Whh2.h2prev --------
    for (int k = 0; k < 2 * nsl; k++) {
      CONSUME_ONE(dot2cur);
      if (issued < ISS_MAX) ISSUE_ONE();
    }
    grid_sync();

    // -------- act1: h1 (bias + P1 folded here; redundant per block) --------
    {
      const float* P = (arow >= 0) ? (g_P1 + (size_t)arow * H4) : (const float*)0;
      int u = tid;
      float di = __ldcg(&g_dot1[u])        + __ldcg(&g_b1[u]);
      float df = __ldcg(&g_dot1[u + 2048]) + __ldcg(&g_b1[u + 2048]);
      float dg = __ldcg(&g_dot1[u + 4096]) + __ldcg(&g_b1[u + 4096]);
      float dz = __ldcg(&g_dot1[u + 6144]) + __ldcg(&g_b1[u + 6144]);
      if (P) {
        di += __ldcg(&P[u]);        df += __ldcg(&P[u + 2048]);
        dg += __ldcg(&P[u + 4096]); dz += __ldcg(&P[u + 6144]);
      }
      float c = sigm(df) * c1a + sigm(di) * tanhf(dg);
      c1a = c;
      sAh[u] = __float2half_rn(sigm(dz) * tanhf(c));
      u = tid + NTH;
      di = __ldcg(&g_dot1[u])        + __ldcg(&g_b1[u]);
      df = __ldcg(&g_dot1[u + 2048]) + __ldcg(&g_b1[u + 2048]);
      dg = __ldcg(&g_dot1[u + 4096]) + __ldcg(&g_b1[u + 4096]);
      dz = __ldcg(&g_dot1[u + 6144]) + __ldcg(&g_b1[u + 6144]);
      if (P) {
        di += __ldcg(&P[u]);        df += __ldcg(&P[u + 2048]);
        dg += __ldcg(&P[u + 4096]); dz += __ldcg(&P[u + 6144]);
      }
      c = sigm(df) * c1b + sigm(di) * tanhf(dg);
      c1b = c;
      sAh[u] = __float2half_rn(sigm(dz) * tanhf(c));
    }
    __syncthreads();

    // -------- segment B: Wih2.h1new --------
    for (int k = 0; k < nsl; k++) {
      CONSUME_ONE(dot2cur);
      if (issued < ISS_MAX) ISSUE_ONE();
    }
    grid_sync();

    // -------- act2: h2 --------
    {
      int u = tid;
      float di = __ldcg(&dot2cur[u])        + __ldcg(&g_dot3[u])        + __ldcg(&g_b2[u]);
      float df = __ldcg(&dot2cur[u + 2048]) + __ldcg(&g_dot3[u + 2048]) + __ldcg(&g_b2[u + 2048]);
      float dg = __ldcg(&dot2cur[u + 4096]) + __ldcg(&g_dot3[u + 4096]) + __ldcg(&g_b2[u + 4096]);
      float dz = __ldcg(&dot2cur[u + 6144]) + __ldcg(&g_dot3[u + 6144]) + __ldcg(&g_b2[u + 6144]);
      float c = sigm(df) * c2a + sigm(di) * tanhf(dg);
      c2a = c;
      sBh[u] = __float2half_rn(sigm(dz) * tanhf(c));
      u = tid + NTH;
      di = __ldcg(&dot2cur[u])        + __ldcg(&g_dot3[u])        + __ldcg(&g_b2[u]);
      df = __ldcg(&dot2cur[u + 2048]) + __ldcg(&g_dot3[u + 2048]) + __ldcg(&g_b2[u + 2048]);
      dg = __ldcg(&dot2cur[u + 4096]) + __ldcg(&g_dot3[u + 4096]) + __ldcg(&g_b2[u + 4096]);
      dz = __ldcg(&dot2cur[u + 6144]) + __ldcg(&g_dot3[u + 6144]) + __ldcg(&g_b2[u + 6144]);
      c = sigm(df) * c2b + sigm(di) * tanhf(dg);
      c2b = c;
      sBh[u] = __float2half_rn(sigm(dz) * tanhf(c));
    }
    __syncthreads();

    // -------- logits (8 parallel warps, redundant per block) --------
    if (w < 8) {
      const float4* wr = (const float4*)(Wout + ((size_t)t * MAXS + w) * HD);
      const __half2* h2p = (const __half2*)(sm + OFF_SBH);
      float p = 0.f;
#pragma unroll 4
      for (int i = lane; i < HD / 4; i += 32) {
        float4 a = __ldg(&wr[i]);
        float2 xf = __half22float2(h2p[2 * i]);
        float2 yf = __half22float2(h2p[2 * i + 1]);
        p += a.x * xf.x + a.y * xf.y + a.z * yf.x + a.w * yf.y;
      }
#pragma unroll
      for (int off = 16; off; off >>= 1) p += __shfl_xor_sync(0xffffffffu, p, off);
      if (lane == 0) sLG[w] = p + bout[t * MAXS + w];
    }
    __syncthreads();

    // -------- finalize sample (thread 0) --------
    if (tid == 0) {
      const int tp = t & 3;
      const int sz = sizes[tp];
      float l[8];
#pragma unroll
      for (int j = 0; j < 8; j++) l[j] = (j < sz) ? sLG[j] : -1e9f;

      unsigned k0, k1;
      threefry2x32(0u, 1u, 0u, (unsigned)t, &k0, &k1);
      unsigned bits[8];
#pragma unroll
      for (int i = 0; i < 8; i++) {
        unsigned a, bb;
        threefry2x32(k0, k1, 0u, (unsigned)i, &a, &bb);
        bits[i] = a ^ bb;
      }
      float gmb[8];
#pragma unroll
      for (int j = 0; j < 8; j++) {
        unsigned fb = (bits[j] >> 9) | 0x3f800000u;
        float uu = __uint_as_float(fb) - 1.0f;
        uu = fmaxf(TINYF, uu + TINYF);
        gmb[j] = -logf(-logf(uu));
      }
      int best = 0;
      float bv = l[0] + gmb[0];
#pragma unroll
      for (int j = 1; j < 8; j++) {
        float v = l[j] + gmb[j];
        if (v > bv) { bv = v; best = j; }
      }
      float m = l[0];
#pragma unroll
      for (int j = 1; j < 8; j++) m = fmaxf(m, l[j]);
      float s = 0.f;
#pragma unroll
      for (int j = 0; j < 8; j++) s += expf(l[j] - m);
      float prob = expf(l[best] - m) / s;

      *sAR = offs[tp] + best;
      if (b == 0) {
        out[t]      = (float)best;
        out[TT + t] = prob;
      }
    }
    __syncthreads();
  }
}

// ------------------------- launch -------------------------------------------
extern "C" void kernel_launch(void* const* d_in, const int* in_sizes, int n_in,
                              void* d_out, int out_size) {
  const float* emb  = (const float*)d_in[0];
  const float* Wih1 = (const float*)d_in[1];
  const float* Whh1 = (const float*)d_in[2];
  const float* bih1 = (const float*)d_in[3];
  const float* bhh1 = (const float*)d_in[4];
  const float* Wih2 = (const float*)d_in[5];
  const float* Whh2 = (const float*)d_in[6];
  const float* bih2 = (const float*)d_in[7];
  const float* bhh2 = (const float*)d_in[8];
  const float* Wout = (const float*)d_in[9];
  const float* bout = (const float*)d_in[10];
  (void)in_sizes; (void)n_in; (void)out_size;

  static int configured = 0;
  if (!configured) {
    cudaFuncSetAttribute(nas_lstm_kernel,
                         cudaFuncAttributeMaxDynamicSharedMemorySize, SMEM_TOTAL);
    configured = 1;
  }

  int dev = 0;
  cudaGetDevice(&dev);
  int sms = 0;
  cudaDeviceGetAttribute(&sms, cudaDevAttrMultiProcessorCount, dev);
  int occ = 0;
  cudaOccupancyMaxActiveBlocksPerMultiprocessor(&occ, nas_lstm_kernel, NTH,
                                                SMEM_TOTAL);
  if (occ < 1) occ = 1;
  int nblk = sms * occ;
  if (nblk > 128) nblk = 128;   // 128*32 warps divide 8192 rows exactly
  if (nblk < 1) nblk = 1;

  nas_lstm_kernel<<<nblk, NTH, SMEM_TOTAL>>>(emb, Wih1, Whh1, bih1, bhh1,
                                             Wih2, Whh2, bih2, bhh2,
                                             Wout, bout, (float*)d_out);
}